// round 1
// baseline (speedup 1.0000x reference)
#include <cuda_runtime.h>
#include <math.h>

#define Bb   2
#define Tt   2048
#define Hh   16
#define Ss   64
#define EMBv 1024
#define NTOK (Bb*Tt)      // 4096 tokens
#define FF   (4*EMBv)     // 4096

// ---------------- scratch (static device globals; no allocation allowed) ----
__device__ float g_kqv[NTOK*Hh*3*Ss]; // [B,T,H,192] k|q|v   (~50MB)
__device__ float g_res[NTOK*EMBv];    // attention output
__device__ float g_mha[NTOK*EMBv];    // proj output
__device__ float g_x1 [NTOK*EMBv];    // after first LN
__device__ float g_h  [NTOK*FF];      // gelu(x1 @ W1 + b)   (~67MB)
__device__ float g_ff [NTOK*EMBv];    // h @ W2 + b

// ---------------- generic tiled fp32 GEMM: C = epi(A[M,K] @ W[K,N] + bias) --
// EPI: 0 = none, 1 = +bias, 2 = +bias then exact GELU
template<int BM,int BN,int BK,int TM,int TN,int EPI>
__global__ __launch_bounds__((BM/TM)*(BN/TN))
void gemm_kernel(const float* __restrict__ A, const float* __restrict__ W,
                 const float* __restrict__ bias, float* __restrict__ C,
                 int M, int N, int K)
{
    constexpr int THREADS = (BM/TM)*(BN/TN);       // 256 in all configs
    __shared__ float As[BK][BM];                   // A stored transposed
    __shared__ float Bs[BK][BN];
    const int tid = threadIdx.x;
    const int tx  = tid % (BN/TN);
    const int ty  = tid / (BN/TN);
    const int row0 = blockIdx.y * BM;
    const int col0 = blockIdx.x * BN;

    float acc[TM][TN];
    #pragma unroll
    for (int i = 0; i < TM; i++)
        #pragma unroll
        for (int j = 0; j < TN; j++) acc[i][j] = 0.f;

    constexpr int AL = BM*BK/(THREADS*4);
    constexpr int BL = BK*BN/(THREADS*4);

    for (int k0 = 0; k0 < K; k0 += BK) {
        #pragma unroll
        for (int i = 0; i < AL; i++) {
            int e = tid + i*THREADS;
            int r = e / (BK/4);
            int kq = e % (BK/4);
            float4 v = *(const float4*)(A + (size_t)(row0 + r)*K + k0 + kq*4);
            As[kq*4+0][r] = v.x; As[kq*4+1][r] = v.y;
            As[kq*4+2][r] = v.z; As[kq*4+3][r] = v.w;
        }
        #pragma unroll
        for (int i = 0; i < BL; i++) {
            int e = tid + i*THREADS;
            int r  = e / (BN/4);
            int cq = e % (BN/4);
            *(float4*)&Bs[r][cq*4] =
                *(const float4*)(W + (size_t)(k0 + r)*N + col0 + cq*4);
        }
        __syncthreads();

        #pragma unroll
        for (int kk = 0; kk < BK; kk++) {
            float a[TM], b[TN];
            #pragma unroll
            for (int i = 0; i < TM; i += 4) {
                float4 t = *(const float4*)&As[kk][ty*TM + i];
                a[i] = t.x; a[i+1] = t.y; a[i+2] = t.z; a[i+3] = t.w;
            }
            #pragma unroll
            for (int j = 0; j < TN; j += 4) {
                float4 t = *(const float4*)&Bs[kk][tx*TN + j];
                b[j] = t.x; b[j+1] = t.y; b[j+2] = t.z; b[j+3] = t.w;
            }
            #pragma unroll
            for (int i = 0; i < TM; i++)
                #pragma unroll
                for (int j = 0; j < TN; j++)
                    acc[i][j] += a[i]*b[j];
        }
        __syncthreads();
    }

    #pragma unroll
    for (int i = 0; i < TM; i++) {
        int r = row0 + ty*TM + i;
        #pragma unroll
        for (int j = 0; j < TN; j += 4) {
            int c = col0 + tx*TN + j;
            float4 v = make_float4(acc[i][j], acc[i][j+1], acc[i][j+2], acc[i][j+3]);
            if (EPI >= 1) {
                v.x += bias[c+0]; v.y += bias[c+1];
                v.z += bias[c+2]; v.w += bias[c+3];
            }
            if (EPI == 2) { // exact GELU: 0.5*x*(1+erf(x/sqrt(2)))
                v.x = 0.5f*v.x*(1.f + erff(v.x*0.70710678118654752f));
                v.y = 0.5f*v.y*(1.f + erff(v.y*0.70710678118654752f));
                v.z = 0.5f*v.z*(1.f + erff(v.z*0.70710678118654752f));
                v.w = 0.5f*v.w*(1.f + erff(v.w*0.70710678118654752f));
            }
            *(float4*)(C + (size_t)r*N + c) = v;
        }
    }
}

// ---------------- flash attention ------------------------------------------
// grid: (B*H, T/64). block: 256 threads. One 64-query tile per block,
// streaming 64-key tiles with online softmax. kqv row stride = H*192.
// Thread (tx,ty): score rows {ty+16i}, key cols {tx+16j}, out cols {4tx..4tx+3}.
__global__ __launch_bounds__(256)
void attn_kernel(const float* __restrict__ kqv, float* __restrict__ res)
{
    constexpr int AP = 68;                     // padded row stride (floats)
    extern __shared__ float sm[];
    float* Qs = sm;                            // 64 x AP
    float* Ks = sm + 64*AP;
    float* Vs = sm + 2*64*AP;
    float* Ps = sm + 3*64*AP;

    const int bh = blockIdx.x;
    const int b  = bh >> 4;
    const int h  = bh & 15;
    const int q0 = blockIdx.y * 64;
    const int tid = threadIdx.x;
    const int tx = tid & 15;
    const int ty = tid >> 4;
    const size_t rstr = (size_t)Hh * 3 * Ss;   // 3072

    // load Q tile (q lives at col offset 64 inside the 192-wide kqv row)
    const float* qb = kqv + ((size_t)(b*Tt + q0)*Hh + h)*192 + 64;
    #pragma unroll
    for (int i = 0; i < 4; i++) {
        int e = tid + i*256;
        int r = e >> 4, cq = e & 15;
        *(float4*)&Qs[r*AP + cq*4] = *(const float4*)(qb + (size_t)r*rstr + cq*4);
    }

    float m[4], l[4], O[4][4];
    #pragma unroll
    for (int i = 0; i < 4; i++) {
        m[i] = -INFINITY; l[i] = 0.f;
        #pragma unroll
        for (int j = 0; j < 4; j++) O[i][j] = 0.f;
    }
    __syncthreads();

    for (int kt = 0; kt < Tt/64; kt++) {
        const float* kb = kqv + ((size_t)(b*Tt + kt*64)*Hh + h)*192;
        #pragma unroll
        for (int i = 0; i < 4; i++) {
            int e = tid + i*256;
            int r = e >> 4, cq = e & 15;
            *(float4*)&Ks[r*AP + cq*4] = *(const float4*)(kb + (size_t)r*rstr + cq*4);
            *(float4*)&Vs[r*AP + cq*4] = *(const float4*)(kb + (size_t)r*rstr + 128 + cq*4);
        }
        __syncthreads();

        float S[4][4];
        #pragma unroll
        for (int i = 0; i < 4; i++)
            #pragma unroll
            for (int j = 0; j < 4; j++) S[i][j] = 0.f;

        #pragma unroll
        for (int kk = 0; kk < 64; kk += 4) {
            float4 q[4], k4[4];
            #pragma unroll
            for (int i = 0; i < 4; i++) q[i]  = *(const float4*)&Qs[(ty + 16*i)*AP + kk];
            #pragma unroll
            for (int j = 0; j < 4; j++) k4[j] = *(const float4*)&Ks[(tx + 16*j)*AP + kk];
            #pragma unroll
            for (int i = 0; i < 4; i++)
                #pragma unroll
                for (int j = 0; j < 4; j++)
                    S[i][j] += q[i].x*k4[j].x + q[i].y*k4[j].y
                             + q[i].z*k4[j].z + q[i].w*k4[j].w;
        }

        // online softmax update (row reduction across the 16 tx lanes)
        #pragma unroll
        for (int i = 0; i < 4; i++) {
            float rm = -INFINITY;
            #pragma unroll
            for (int j = 0; j < 4; j++) { S[i][j] *= 0.125f; rm = fmaxf(rm, S[i][j]); }
            #pragma unroll
            for (int off = 8; off > 0; off >>= 1)
                rm = fmaxf(rm, __shfl_xor_sync(0xffffffffu, rm, off, 16));
            float mn = fmaxf(m[i], rm);
            float sc = __expf(m[i] - mn);
            float rs = 0.f;
            #pragma unroll
            for (int j = 0; j < 4; j++) { float p = __expf(S[i][j] - mn); S[i][j] = p; rs += p; }
            #pragma unroll
            for (int off = 8; off > 0; off >>= 1)
                rs += __shfl_xor_sync(0xffffffffu, rs, off, 16);
            l[i] = l[i]*sc + rs;
            m[i] = mn;
            #pragma unroll
            for (int j = 0; j < 4; j++) O[i][j] *= sc;
            #pragma unroll
            for (int j = 0; j < 4; j++) Ps[(ty + 16*i)*AP + tx + 16*j] = S[i][j];
        }
        __syncthreads();

        // O += P @ V
        #pragma unroll
        for (int j0 = 0; j0 < 64; j0 += 4) {
            float pr[4][4];
            #pragma unroll
            for (int i = 0; i < 4; i++) {
                float4 p = *(const float4*)&Ps[(ty + 16*i)*AP + j0];
                pr[i][0] = p.x; pr[i][1] = p.y; pr[i][2] = p.z; pr[i][3] = p.w;
            }
            #pragma unroll
            for (int jj = 0; jj < 4; jj++) {
                float4 v = *(const float4*)&Vs[(j0 + jj)*AP + tx*4];
                #pragma unroll
                for (int i = 0; i < 4; i++) {
                    float p = pr[i][jj];
                    O[i][0] += p*v.x; O[i][1] += p*v.y;
                    O[i][2] += p*v.z; O[i][3] += p*v.w;
                }
            }
        }
        __syncthreads();
    }

    #pragma unroll
    for (int i = 0; i < 4; i++) {
        float inv = 1.f / l[i];
        int t = q0 + ty + 16*i;
        float4 o = make_float4(O[i][0]*inv, O[i][1]*inv, O[i][2]*inv, O[i][3]*inv);
        *(float4*)(res + ((size_t)(b*Tt + t))*EMBv + h*64 + tx*4) = o;
    }
}

// ---------------- fused residual add + LayerNorm ---------------------------
__global__ __launch_bounds__(256)
void add_ln_kernel(const float* __restrict__ xa, const float* __restrict__ xb,
                   const float* __restrict__ g, const float* __restrict__ bt,
                   float* __restrict__ out)
{
    const int row = blockIdx.x;
    const int tid = threadIdx.x;
    const float* pa = xa + (size_t)row*EMBv;
    const float* pb = xb + (size_t)row*EMBv;
    float v[4], s = 0.f, s2 = 0.f;
    #pragma unroll
    for (int i = 0; i < 4; i++) {
        int c = tid + i*256;
        v[i] = pa[c] + pb[c];
        s += v[i]; s2 += v[i]*v[i];
    }
    #pragma unroll
    for (int off = 16; off > 0; off >>= 1) {
        s  += __shfl_xor_sync(0xffffffffu, s,  off);
        s2 += __shfl_xor_sync(0xffffffffu, s2, off);
    }
    __shared__ float rs[8], rs2[8];
    int w = tid >> 5, lane = tid & 31;
    if (lane == 0) { rs[w] = s; rs2[w] = s2; }
    __syncthreads();
    if (w == 0) {
        float a  = (lane < 8) ? rs[lane]  : 0.f;
        float a2 = (lane < 8) ? rs2[lane] : 0.f;
        #pragma unroll
        for (int off = 4; off > 0; off >>= 1) {
            a  += __shfl_xor_sync(0xffffffffu, a,  off);
            a2 += __shfl_xor_sync(0xffffffffu, a2, off);
        }
        if (lane == 0) { rs[0] = a; rs2[0] = a2; }
    }
    __syncthreads();
    float mean = rs[0] * (1.f/EMBv);
    float var  = rs2[0] * (1.f/EMBv) - mean*mean;
    float inv  = rsqrtf(var + 1e-5f);
    #pragma unroll
    for (int i = 0; i < 4; i++) {
        int c = tid + i*256;
        out[(size_t)row*EMBv + c] = (v[i] - mean)*inv*g[c] + bt[c];
    }
}

// ---------------- launch ----------------------------------------------------
extern "C" void kernel_launch(void* const* d_in, const int* in_sizes, int n_in,
                              void* d_out, int out_size)
{
    const float* x     = (const float*)d_in[0];
    const float* Wkqv  = (const float*)d_in[1];
    const float* Wproj = (const float*)d_in[2];
    const float* g1    = (const float*)d_in[3];
    const float* b1    = (const float*)d_in[4];
    const float* W1    = (const float*)d_in[5];
    const float* bff1  = (const float*)d_in[6];
    const float* W2    = (const float*)d_in[7];
    const float* bff2  = (const float*)d_in[8];
    const float* g2    = (const float*)d_in[9];
    const float* b2    = (const float*)d_in[10];
    float* out = (float*)d_out;

    float *kqv, *res, *mha, *x1, *hbuf, *ff;
    cudaGetSymbolAddress((void**)&kqv,  g_kqv);
    cudaGetSymbolAddress((void**)&res,  g_res);
    cudaGetSymbolAddress((void**)&mha,  g_mha);
    cudaGetSymbolAddress((void**)&x1,   g_x1);
    cudaGetSymbolAddress((void**)&hbuf, g_h);
    cudaGetSymbolAddress((void**)&ff,   g_ff);

    // 1) kqv = reshape(x,[B*T*H,64]) @ Wkqv[64,192]
    gemm_kernel<128,64,16,8,4,0><<<dim3(3, (NTOK*Hh)/128), 256>>>(
        x, Wkqv, nullptr, kqv, NTOK*Hh, 3*Ss, Ss);

    // 2) attention -> res [B,T,EMB]
    const int attn_smem = 4*64*68*(int)sizeof(float); // 69632 B
    cudaFuncSetAttribute(attn_kernel,
                         cudaFuncAttributeMaxDynamicSharedMemorySize, attn_smem);
    attn_kernel<<<dim3(Bb*Hh, Tt/64), 256, attn_smem>>>(kqv, res);

    // 3) mha = res @ Wproj
    gemm_kernel<128,128,16,8,8,0><<<dim3(EMBv/128, NTOK/128), 256>>>(
        res, Wproj, nullptr, mha, NTOK, EMBv, EMBv);

    // 4) x1 = LN(x + mha)
    add_ln_kernel<<<NTOK, 256>>>(x, mha, g1, b1, x1);

    // 5) h = gelu(x1 @ W1 + bff1)
    gemm_kernel<128,128,16,8,8,2><<<dim3(FF/128, NTOK/128), 256>>>(
        x1, W1, bff1, hbuf, NTOK, FF, EMBv);

    // 6) ff = h @ W2 + bff2
    gemm_kernel<128,128,16,8,8,1><<<dim3(EMBv/128, NTOK/128), 256>>>(
        hbuf, W2, bff2, ff, NTOK, EMBv, FF);

    // 7) out = LN(x1 + ff)
    add_ln_kernel<<<NTOK, 256>>>(x1, ff, g2, b2, out);
}

// round 3
// speedup vs baseline: 1.9893x; 1.9893x over previous
#include <cuda_runtime.h>
#include <math.h>
#include <stdint.h>

#define Bb   2
#define Tt   2048
#define Hh   16
#define Ss   64
#define EMBv 1024
#define NTOK (Bb*Tt)      // 4096 tokens
#define FF   (4*EMBv)     // 4096

// ---------------- scratch (static device globals; no allocation allowed) ----
__device__ float g_kqv[NTOK*Hh*3*Ss]; // [B,T,H,192] k|q|v
__device__ float g_res[NTOK*EMBv];    // attention output (tf32-rounded)
__device__ float g_mha[NTOK*EMBv];    // proj output (exact)
__device__ float g_x1 [NTOK*EMBv];    // after first LN (exact)
__device__ float g_x1r[NTOK*EMBv];    // after first LN (tf32-rounded copy)
__device__ float g_h  [NTOK*FF];      // gelu(...) (tf32-rounded)
__device__ float g_ff [NTOK*EMBv];    // h @ W2 + b (exact)
__device__ float g_wtp[EMBv*EMBv];    // Wproj^T  [N,K] tf32-rounded
__device__ float g_wt1[EMBv*FF];      // W1^T     tf32-rounded
__device__ float g_wt2[FF*EMBv];      // W2^T     tf32-rounded

// ======================= helpers ===========================================
__device__ __forceinline__ uint32_t smem_u32(const void* p) {
    uint32_t a;
    asm("{ .reg .u64 t; cvta.to.shared.u64 t, %1; cvt.u32.u64 %0, t; }"
        : "=r"(a) : "l"(p));
    return a;
}
__device__ __forceinline__ void cpa16(uint32_t s, const void* g) {
    asm volatile("cp.async.cg.shared.global [%0], [%1], 16;\n" :: "r"(s), "l"(g));
}
__device__ __forceinline__ float tf32r(float x) {
    uint32_t u;
    asm("cvt.rna.tf32.f32 %0, %1;" : "=r"(u) : "f"(x));
    return __uint_as_float(u);
}
__device__ __forceinline__ void mma_tf32(float* c, const uint32_t* a, const uint32_t* b) {
    asm volatile(
        "mma.sync.aligned.m16n8k8.row.col.f32.tf32.tf32.f32 "
        "{%0,%1,%2,%3}, {%4,%5,%6,%7}, {%8,%9}, {%0,%1,%2,%3};"
        : "+f"(c[0]), "+f"(c[1]), "+f"(c[2]), "+f"(c[3])
        : "r"(a[0]), "r"(a[1]), "r"(a[2]), "r"(a[3]), "r"(b[0]), "r"(b[1]));
}

// ======================= weight transpose + tf32 round ======================
__global__ __launch_bounds__(256)
void transpose_kernel(const float* __restrict__ in, float* __restrict__ out,
                      int R, int C)
{
    __shared__ float t[32][33];
    const int tx = threadIdx.x, ty = threadIdx.y;
    const int c = blockIdx.x * 32 + tx;
    const int r0 = blockIdx.y * 32;
    #pragma unroll
    for (int i = 0; i < 32; i += 8)
        t[ty + i][tx] = in[(size_t)(r0 + ty + i) * C + c];
    __syncthreads();
    const int oc = blockIdx.y * 32 + tx;
    const int or0 = blockIdx.x * 32;
    #pragma unroll
    for (int i = 0; i < 32; i += 8)
        out[(size_t)(or0 + ty + i) * R + oc] = tf32r(t[tx][ty + i]);
}

// ======================= tf32 mma.sync GEMM ================================
// C[M,N] = epi(A[M,K] @ Bt[N,K]^T + bias).  128x128 CTA tile, BK=32,
// 8 warps each 64x32, m16n8k8 tf32. A/Bt must already be tf32-rounded.
// EPI: 0 none, 1 +bias, 2 +bias+GELU (output also tf32-rounded)
#define MMA_LD    36
#define MMA_TILEF (128*MMA_LD)                 // floats per matrix per stage
#define MMA_SMEM  (2*2*MMA_TILEF*(int)sizeof(float))   // 73728 B

template<int EPI>
__global__ __launch_bounds__(256, 2)
void mma_gemm(const float* __restrict__ A, const float* __restrict__ Bt,
              const float* __restrict__ bias, float* __restrict__ C,
              int M, int N, int K)
{
    extern __shared__ float sm[];
    const int tid  = threadIdx.x;
    const int lane = tid & 31;
    const int wid  = tid >> 5;
    const int m0 = (wid & 1) * 64;
    const int n0 = (wid >> 1) * 32;
    const int row0 = blockIdx.y * 128;
    const int col0 = blockIdx.x * 128;
    const int lq = lane >> 2;      // 0..7
    const int lr = lane & 3;       // 0..3

    float acc[4][4][4];
    #pragma unroll
    for (int i = 0; i < 4; i++)
        #pragma unroll
        for (int j = 0; j < 4; j++)
            #pragma unroll
            for (int k = 0; k < 4; k++) acc[i][j][k] = 0.f;

    auto issue = [&](int kt, int s) {
        const int k0 = kt * 32;
        float* dstA = sm + s * 2 * MMA_TILEF;
        float* dstB = dstA + MMA_TILEF;
        #pragma unroll
        for (int i = 0; i < 4; i++) {
            int e = tid + i * 256;
            int r = e >> 3, c4 = e & 7;
            cpa16(smem_u32(dstA + r * MMA_LD + c4 * 4),
                  A  + (size_t)(row0 + r) * K + k0 + c4 * 4);
            cpa16(smem_u32(dstB + r * MMA_LD + c4 * 4),
                  Bt + (size_t)(col0 + r) * K + k0 + c4 * 4);
        }
        asm volatile("cp.async.commit_group;" ::: "memory");
    };

    const int NK = K / 32;
    issue(0, 0);

    for (int kt = 0; kt < NK; kt++) {
        const int s = kt & 1;
        if (kt + 1 < NK) {
            issue(kt + 1, s ^ 1);
            asm volatile("cp.async.wait_group 1;" ::: "memory");
        } else {
            asm volatile("cp.async.wait_group 0;" ::: "memory");
        }
        __syncthreads();

        const float* sA = sm + s * 2 * MMA_TILEF;
        const float* sB = sA + MMA_TILEF;

        #pragma unroll
        for (int kk = 0; kk < 32; kk += 8) {
            const int kr = kk + lr;
            uint32_t a[4][4], b[4][2];
            #pragma unroll
            for (int mi = 0; mi < 4; mi++) {
                int m = m0 + mi * 16 + lq;
                a[mi][0] = __float_as_uint(sA[(size_t)m       * MMA_LD + kr]);
                a[mi][1] = __float_as_uint(sA[(size_t)(m + 8) * MMA_LD + kr]);
                a[mi][2] = __float_as_uint(sA[(size_t)m       * MMA_LD + kr + 4]);
                a[mi][3] = __float_as_uint(sA[(size_t)(m + 8) * MMA_LD + kr + 4]);
            }
            #pragma unroll
            for (int ni = 0; ni < 4; ni++) {
                int n = n0 + ni * 8 + lq;
                b[ni][0] = __float_as_uint(sB[(size_t)n * MMA_LD + kr]);
                b[ni][1] = __float_as_uint(sB[(size_t)n * MMA_LD + kr + 4]);
            }
            #pragma unroll
            for (int mi = 0; mi < 4; mi++)
                #pragma unroll
                for (int ni = 0; ni < 4; ni++)
                    mma_tf32(acc[mi][ni], a[mi], b[ni]);
        }
        __syncthreads();
    }

    // epilogue: c0,c1 at (row lq, cols 2*lr, 2*lr+1); c2,c3 at row lq+8
    #pragma unroll
    for (int mi = 0; mi < 4; mi++) {
        #pragma unroll
        for (int half = 0; half < 2; half++) {
            const int r = row0 + m0 + mi * 16 + lq + half * 8;
            #pragma unroll
            for (int ni = 0; ni < 4; ni++) {
                const int c = col0 + n0 + ni * 8 + 2 * lr;
                float vx = acc[mi][ni][half * 2 + 0];
                float vy = acc[mi][ni][half * 2 + 1];
                if (EPI >= 1) { vx += bias[c]; vy += bias[c + 1]; }
                if (EPI == 2) {
                    vx = 0.5f * vx * (1.f + erff(vx * 0.70710678118654752f));
                    vy = 0.5f * vy * (1.f + erff(vy * 0.70710678118654752f));
                    vx = tf32r(vx); vy = tf32r(vy);
                }
                float2 v = make_float2(vx, vy);
                *(float2*)(C + (size_t)r * N + c) = v;
            }
        }
    }
}

// ---------------- fp32 SGEMM (kqv: K=64, N=192) ----------------------------
template<int BM,int BN,int BK,int TM,int TN>
__global__ __launch_bounds__((BM/TM)*(BN/TN))
void gemm_kernel(const float* __restrict__ A, const float* __restrict__ W,
                 float* __restrict__ C, int M, int N, int K)
{
    constexpr int THREADS = (BM/TM)*(BN/TN);
    __shared__ float As[BK][BM];
    __shared__ float Bs[BK][BN];
    const int tid = threadIdx.x;
    const int tx  = tid % (BN/TN);
    const int ty  = tid / (BN/TN);
    const int row0 = blockIdx.y * BM;
    const int col0 = blockIdx.x * BN;

    float acc[TM][TN];
    #pragma unroll
    for (int i = 0; i < TM; i++)
        #pragma unroll
        for (int j = 0; j < TN; j++) acc[i][j] = 0.f;

    constexpr int AL = BM*BK/(THREADS*4);
    constexpr int BL = BK*BN/(THREADS*4);

    for (int k0 = 0; k0 < K; k0 += BK) {
        #pragma unroll
        for (int i = 0; i < AL; i++) {
            int e = tid + i*THREADS;
            int r = e / (BK/4);
            int kq = e % (BK/4);
            float4 v = *(const float4*)(A + (size_t)(row0 + r)*K + k0 + kq*4);
            As[kq*4+0][r] = v.x; As[kq*4+1][r] = v.y;
            As[kq*4+2][r] = v.z; As[kq*4+3][r] = v.w;
        }
        #pragma unroll
        for (int i = 0; i < BL; i++) {
            int e = tid + i*THREADS;
            int r  = e / (BN/4);
            int cq = e % (BN/4);
            *(float4*)&Bs[r][cq*4] =
                *(const float4*)(W + (size_t)(k0 + r)*N + col0 + cq*4);
        }
        __syncthreads();
        #pragma unroll
        for (int kk = 0; kk < BK; kk++) {
            float a[TM], b[TN];
            #pragma unroll
            for (int i = 0; i < TM; i += 4) {
                float4 t = *(const float4*)&As[kk][ty*TM + i];
                a[i] = t.x; a[i+1] = t.y; a[i+2] = t.z; a[i+3] = t.w;
            }
            #pragma unroll
            for (int j = 0; j < TN; j += 4) {
                float4 t = *(const float4*)&Bs[kk][tx*TN + j];
                b[j] = t.x; b[j+1] = t.y; b[j+2] = t.z; b[j+3] = t.w;
            }
            #pragma unroll
            for (int i = 0; i < TM; i++)
                #pragma unroll
                for (int j = 0; j < TN; j++)
                    acc[i][j] += a[i]*b[j];
        }
        __syncthreads();
    }
    #pragma unroll
    for (int i = 0; i < TM; i++) {
        int r = row0 + ty*TM + i;
        #pragma unroll
        for (int j = 0; j < TN; j += 4) {
            int c = col0 + tx*TN + j;
            float4 v = make_float4(acc[i][j], acc[i][j+1], acc[i][j+2], acc[i][j+3]);
            *(float4*)(C + (size_t)r*N + c) = v;
        }
    }
}

// ---------------- flash attention (fp32; output tf32-rounded) ---------------
__global__ __launch_bounds__(256)
void attn_kernel(const float* __restrict__ kqv, float* __restrict__ res)
{
    constexpr int AP = 68;
    extern __shared__ float sm[];
    float* Qs = sm;
    float* Ks = sm + 64*AP;
    float* Vs = sm + 2*64*AP;
    float* Ps = sm + 3*64*AP;

    const int bh = blockIdx.x;
    const int b  = bh >> 4;
    const int h  = bh & 15;
    const int q0 = blockIdx.y * 64;
    const int tid = threadIdx.x;
    const int tx = tid & 15;
    const int ty = tid >> 4;
    const size_t rstr = (size_t)Hh * 3 * Ss;

    const float* qb = kqv + ((size_t)(b*Tt + q0)*Hh + h)*192 + 64;
    #pragma unroll
    for (int i = 0; i < 4; i++) {
        int e = tid + i*256;
        int r = e >> 4, cq = e & 15;
        *(float4*)&Qs[r*AP + cq*4] = *(const float4*)(qb + (size_t)r*rstr + cq*4);
    }

    float m[4], l[4], O[4][4];
    #pragma unroll
    for (int i = 0; i < 4; i++) {
        m[i] = -INFINITY; l[i] = 0.f;
        #pragma unroll
        for (int j = 0; j < 4; j++) O[i][j] = 0.f;
    }
    __syncthreads();

    for (int kt = 0; kt < Tt/64; kt++) {
        const float* kb = kqv + ((size_t)(b*Tt + kt*64)*Hh + h)*192;
        #pragma unroll
        for (int i = 0; i < 4; i++) {
            int e = tid + i*256;
            int r = e >> 4, cq = e & 15;
            *(float4*)&Ks[r*AP + cq*4] = *(const float4*)(kb + (size_t)r*rstr + cq*4);
            *(float4*)&Vs[r*AP + cq*4] = *(const float4*)(kb + (size_t)r*rstr + 128 + cq*4);
        }
        __syncthreads();

        float S[4][4];
        #pragma unroll
        for (int i = 0; i < 4; i++)
            #pragma unroll
            for (int j = 0; j < 4; j++) S[i][j] = 0.f;

        #pragma unroll
        for (int kk = 0; kk < 64; kk += 4) {
            float4 q[4], k4[4];
            #pragma unroll
            for (int i = 0; i < 4; i++) q[i]  = *(const float4*)&Qs[(ty + 16*i)*AP + kk];
            #pragma unroll
            for (int j = 0; j < 4; j++) k4[j] = *(const float4*)&Ks[(tx + 16*j)*AP + kk];
            #pragma unroll
            for (int i = 0; i < 4; i++)
                #pragma unroll
                for (int j = 0; j < 4; j++)
                    S[i][j] += q[i].x*k4[j].x + q[i].y*k4[j].y
                             + q[i].z*k4[j].z + q[i].w*k4[j].w;
        }

        #pragma unroll
        for (int i = 0; i < 4; i++) {
            float rm = -INFINITY;
            #pragma unroll
            for (int j = 0; j < 4; j++) { S[i][j] *= 0.125f; rm = fmaxf(rm, S[i][j]); }
            #pragma unroll
            for (int off = 8; off > 0; off >>= 1)
                rm = fmaxf(rm, __shfl_xor_sync(0xffffffffu, rm, off, 16));
            float mn = fmaxf(m[i], rm);
            float sc = __expf(m[i] - mn);
            float rs = 0.f;
            #pragma unroll
            for (int j = 0; j < 4; j++) { float p = __expf(S[i][j] - mn); S[i][j] = p; rs += p; }
            #pragma unroll
            for (int off = 8; off > 0; off >>= 1)
                rs += __shfl_xor_sync(0xffffffffu, rs, off, 16);
            l[i] = l[i]*sc + rs;
            m[i] = mn;
            #pragma unroll
            for (int j = 0; j < 4; j++) O[i][j] *= sc;
            #pragma unroll
            for (int j = 0; j < 4; j++) Ps[(ty + 16*i)*AP + tx + 16*j] = S[i][j];
        }
        __syncthreads();

        #pragma unroll
        for (int j0 = 0; j0 < 64; j0 += 4) {
            float pr[4][4];
            #pragma unroll
            for (int i = 0; i < 4; i++) {
                float4 p = *(const float4*)&Ps[(ty + 16*i)*AP + j0];
                pr[i][0] = p.x; pr[i][1] = p.y; pr[i][2] = p.z; pr[i][3] = p.w;
            }
            #pragma unroll
            for (int jj = 0; jj < 4; jj++) {
                float4 v = *(const float4*)&Vs[(j0 + jj)*AP + tx*4];
                #pragma unroll
                for (int i = 0; i < 4; i++) {
                    float p = pr[i][jj];
                    O[i][0] += p*v.x; O[i][1] += p*v.y;
                    O[i][2] += p*v.z; O[i][3] += p*v.w;
                }
            }
        }
        __syncthreads();
    }

    #pragma unroll
    for (int i = 0; i < 4; i++) {
        float inv = 1.f / l[i];
        int t = q0 + ty + 16*i;
        float4 o = make_float4(tf32r(O[i][0]*inv), tf32r(O[i][1]*inv),
                               tf32r(O[i][2]*inv), tf32r(O[i][3]*inv));
        *(float4*)(res + ((size_t)(b*Tt + t))*EMBv + h*64 + tx*4) = o;
    }
}

// ---------------- fused residual add + LayerNorm ---------------------------
// out exact; out_r (optional) = tf32-rounded copy for the downstream GEMM
__global__ __launch_bounds__(256)
void add_ln_kernel(const float* __restrict__ xa, const float* __restrict__ xb,
                   const float* __restrict__ g, const float* __restrict__ bt,
                   float* __restrict__ out, float* __restrict__ out_r)
{
    const int row = blockIdx.x;
    const int tid = threadIdx.x;
    const float* pa = xa + (size_t)row*EMBv;
    const float* pb = xb + (size_t)row*EMBv;
    float v[4], s = 0.f, s2 = 0.f;
    #pragma unroll
    for (int i = 0; i < 4; i++) {
        int c = tid + i*256;
        v[i] = pa[c] + pb[c];
        s += v[i]; s2 += v[i]*v[i];
    }
    #pragma unroll
    for (int off = 16; off > 0; off >>= 1) {
        s  += __shfl_xor_sync(0xffffffffu, s,  off);
        s2 += __shfl_xor_sync(0xffffffffu, s2, off);
    }
    __shared__ float rs[8], rs2[8];
    int w = tid >> 5, lane = tid & 31;
    if (lane == 0) { rs[w] = s; rs2[w] = s2; }
    __syncthreads();
    if (w == 0) {
        float a  = (lane < 8) ? rs[lane]  : 0.f;
        float a2 = (lane < 8) ? rs2[lane] : 0.f;
        #pragma unroll
        for (int off = 4; off > 0; off >>= 1) {
            a  += __shfl_xor_sync(0xffffffffu, a,  off);
            a2 += __shfl_xor_sync(0xffffffffu, a2, off);
        }
        if (lane == 0) { rs[0] = a; rs2[0] = a2; }
    }
    __syncthreads();
    float mean = rs[0] * (1.f/EMBv);
    float var  = rs2[0] * (1.f/EMBv) - mean*mean;
    float inv  = rsqrtf(var + 1e-5f);
    #pragma unroll
    for (int i = 0; i < 4; i++) {
        int c = tid + i*256;
        float o = (v[i] - mean)*inv*g[c] + bt[c];
        out[(size_t)row*EMBv + c] = o;
        if (out_r) out_r[(size_t)row*EMBv + c] = tf32r(o);
    }
}

// ---------------- launch ----------------------------------------------------
extern "C" void kernel_launch(void* const* d_in, const int* in_sizes, int n_in,
                              void* d_out, int out_size)
{
    const float* x     = (const float*)d_in[0];
    const float* Wkqv  = (const float*)d_in[1];
    const float* Wproj = (const float*)d_in[2];
    const float* g1    = (const float*)d_in[3];
    const float* b1    = (const float*)d_in[4];
    const float* W1    = (const float*)d_in[5];
    const float* bff1  = (const float*)d_in[6];
    const float* W2    = (const float*)d_in[7];
    const float* bff2  = (const float*)d_in[8];
    const float* g2    = (const float*)d_in[9];
    const float* b2    = (const float*)d_in[10];
    float* out = (float*)d_out;

    float *kqv, *res, *mha, *x1, *x1r, *hbuf, *ff, *wtp, *wt1, *wt2;
    cudaGetSymbolAddress((void**)&kqv,  g_kqv);
    cudaGetSymbolAddress((void**)&res,  g_res);
    cudaGetSymbolAddress((void**)&mha,  g_mha);
    cudaGetSymbolAddress((void**)&x1,   g_x1);
    cudaGetSymbolAddress((void**)&x1r,  g_x1r);
    cudaGetSymbolAddress((void**)&hbuf, g_h);
    cudaGetSymbolAddress((void**)&ff,   g_ff);
    cudaGetSymbolAddress((void**)&wtp,  g_wtp);
    cudaGetSymbolAddress((void**)&wt1,  g_wt1);
    cudaGetSymbolAddress((void**)&wt2,  g_wt2);

    cudaFuncSetAttribute(mma_gemm<0>, cudaFuncAttributeMaxDynamicSharedMemorySize, MMA_SMEM);
    cudaFuncSetAttribute(mma_gemm<1>, cudaFuncAttributeMaxDynamicSharedMemorySize, MMA_SMEM);
    cudaFuncSetAttribute(mma_gemm<2>, cudaFuncAttributeMaxDynamicSharedMemorySize, MMA_SMEM);

    // 0) transpose + tf32-round weights to [N,K]
    transpose_kernel<<<dim3(EMBv/32, EMBv/32), dim3(32,8)>>>(Wproj, wtp, EMBv, EMBv);
    transpose_kernel<<<dim3(FF/32,   EMBv/32), dim3(32,8)>>>(W1,    wt1, EMBv, FF);
    transpose_kernel<<<dim3(EMBv/32, FF/32),   dim3(32,8)>>>(W2,    wt2, FF,   EMBv);

    // 1) kqv = reshape(x,[B*T*H,64]) @ Wkqv[64,192]  (fp32 SGEMM)
    gemm_kernel<128,64,16,8,4><<<dim3(3, (NTOK*Hh)/128), 256>>>(
        x, Wkqv, kqv, NTOK*Hh, 3*Ss, Ss);

    // 2) attention -> res (tf32-rounded)
    const int attn_smem = 4*64*68*(int)sizeof(float);
    cudaFuncSetAttribute(attn_kernel,
                         cudaFuncAttributeMaxDynamicSharedMemorySize, attn_smem);
    attn_kernel<<<dim3(Bb*Hh, Tt/64), 256, attn_smem>>>(kqv, res);

    // 3) mha = res @ Wproj            (tf32 mma.sync)
    mma_gemm<0><<<dim3(EMBv/128, NTOK/128), 256, MMA_SMEM>>>(
        res, wtp, nullptr, mha, NTOK, EMBv, EMBv);

    // 4) x1 = LN(x + mha)  (+rounded copy x1r)
    add_ln_kernel<<<NTOK, 256>>>(x, mha, g1, b1, x1, x1r);

    // 5) h = gelu(x1 @ W1 + bff1)     (tf32 mma.sync; rounded output)
    mma_gemm<2><<<dim3(FF/128, NTOK/128), 256, MMA_SMEM>>>(
        x1r, wt1, bff1, hbuf, NTOK, FF, EMBv);

    // 6) ff = h @ W2 + bff2           (tf32 mma.sync)
    mma_gemm<1><<<dim3(EMBv/128, NTOK/128), 256, MMA_SMEM>>>(
        hbuf, wt2, bff2, ff, NTOK, EMBv, FF);

    // 7) out = LN(x1 + ff)
    add_ln_kernel<<<NTOK, 256>>>(x1, ff, g2, b2, out, nullptr);
}

// round 4
// speedup vs baseline: 3.0831x; 1.5498x over previous
#include <cuda_runtime.h>
#include <math.h>
#include <stdint.h>

#define Bb   2
#define Tt   2048
#define Hh   16
#define Ss   64
#define EMBv 1024
#define NTOK (Bb*Tt)      // 4096 tokens
#define FF   (4*EMBv)     // 4096

// ---------------- scratch (static device globals; no allocation allowed) ----
__device__ float g_kqv[NTOK*Hh*3*Ss]; // [B,T,H,192] k|q|v  (tf32-rounded)
__device__ float g_res[NTOK*EMBv];    // attention output (tf32-rounded)
__device__ float g_mha[NTOK*EMBv];    // proj output (exact)
__device__ float g_x1 [NTOK*EMBv];    // after first LN (exact)
__device__ float g_x1r[NTOK*EMBv];    // after first LN (tf32-rounded copy)
__device__ float g_h  [NTOK*FF];      // gelu(...) (tf32-rounded)
__device__ float g_ff [NTOK*EMBv];    // h @ W2 + b (exact)
__device__ float g_wtp[EMBv*EMBv];    // Wproj^T  [N,K] tf32-rounded
__device__ float g_wt1[EMBv*FF];      // W1^T     tf32-rounded
__device__ float g_wt2[FF*EMBv];      // W2^T     tf32-rounded

// ======================= helpers ===========================================
__device__ __forceinline__ uint32_t smem_u32(const void* p) {
    uint32_t a;
    asm("{ .reg .u64 t; cvta.to.shared.u64 t, %1; cvt.u32.u64 %0, t; }"
        : "=r"(a) : "l"(p));
    return a;
}
__device__ __forceinline__ void cpa16(uint32_t s, const void* g) {
    asm volatile("cp.async.cg.shared.global [%0], [%1], 16;\n" :: "r"(s), "l"(g));
}
__device__ __forceinline__ float tf32r(float x) {
    uint32_t u;
    asm("cvt.rna.tf32.f32 %0, %1;" : "=r"(u) : "f"(x));
    return __uint_as_float(u);
}
__device__ __forceinline__ void mma_tf32(float* c, const uint32_t* a, const uint32_t* b) {
    asm volatile(
        "mma.sync.aligned.m16n8k8.row.col.f32.tf32.tf32.f32 "
        "{%0,%1,%2,%3}, {%4,%5,%6,%7}, {%8,%9}, {%0,%1,%2,%3};"
        : "+f"(c[0]), "+f"(c[1]), "+f"(c[2]), "+f"(c[3])
        : "r"(a[0]), "r"(a[1]), "r"(a[2]), "r"(a[3]), "r"(b[0]), "r"(b[1]));
}

// ======================= weight transpose + tf32 round ======================
__global__ __launch_bounds__(256)
void transpose_kernel(const float* __restrict__ in, float* __restrict__ out,
                      int R, int C)
{
    __shared__ float t[32][33];
    const int tx = threadIdx.x, ty = threadIdx.y;
    const int c = blockIdx.x * 32 + tx;
    const int r0 = blockIdx.y * 32;
    #pragma unroll
    for (int i = 0; i < 32; i += 8)
        t[ty + i][tx] = in[(size_t)(r0 + ty + i) * C + c];
    __syncthreads();
    const int oc = blockIdx.y * 32 + tx;
    const int or0 = blockIdx.x * 32;
    #pragma unroll
    for (int i = 0; i < 32; i += 8)
        out[(size_t)(or0 + ty + i) * R + oc] = tf32r(t[tx][ty + i]);
}

// ======================= tf32 mma.sync GEMM (3-stage) ======================
// C[M,N] = epi(A[M,K] @ Bt[N,K]^T + bias). 128x128 CTA, BK=32, 8 warps 64x32.
// EPI: 0 none, 1 +bias, 2 +bias+GELU (output tf32-rounded)
#define MMA_LD    36
#define MMA_TILEF (128*MMA_LD)
#define MMA_SMEM  (3*2*MMA_TILEF*(int)sizeof(float))    // 110592 B

template<int EPI>
__global__ __launch_bounds__(256, 2)
void mma_gemm(const float* __restrict__ A, const float* __restrict__ Bt,
              const float* __restrict__ bias, float* __restrict__ C,
              int M, int N, int K)
{
    extern __shared__ float sm[];
    const int tid  = threadIdx.x;
    const int lane = tid & 31;
    const int wid  = tid >> 5;
    const int m0 = (wid & 1) * 64;
    const int n0 = (wid >> 1) * 32;
    const int row0 = blockIdx.y * 128;
    const int col0 = blockIdx.x * 128;
    const int lq = lane >> 2;
    const int lr = lane & 3;

    float acc[4][4][4];
    #pragma unroll
    for (int i = 0; i < 4; i++)
        #pragma unroll
        for (int j = 0; j < 4; j++)
            #pragma unroll
            for (int k = 0; k < 4; k++) acc[i][j][k] = 0.f;

    auto issue = [&](int kt, int s) {
        const int k0 = kt * 32;
        float* dstA = sm + s * 2 * MMA_TILEF;
        float* dstB = dstA + MMA_TILEF;
        #pragma unroll
        for (int i = 0; i < 4; i++) {
            int e = tid + i * 256;
            int r = e >> 3, c4 = e & 7;
            cpa16(smem_u32(dstA + r * MMA_LD + c4 * 4),
                  A  + (size_t)(row0 + r) * K + k0 + c4 * 4);
            cpa16(smem_u32(dstB + r * MMA_LD + c4 * 4),
                  Bt + (size_t)(col0 + r) * K + k0 + c4 * 4);
        }
        asm volatile("cp.async.commit_group;" ::: "memory");
    };

    const int NK = K / 32;
    issue(0, 0);
    issue(1, 1);

    for (int kt = 0; kt < NK; kt++) {
        const int s = kt % 3;
        if (kt == NK - 1) asm volatile("cp.async.wait_group 0;" ::: "memory");
        else              asm volatile("cp.async.wait_group 1;" ::: "memory");
        __syncthreads();
        if (kt + 2 < NK) issue(kt + 2, (kt + 2) % 3);

        const float* sA = sm + s * 2 * MMA_TILEF;
        const float* sB = sA + MMA_TILEF;

        #pragma unroll
        for (int kk = 0; kk < 32; kk += 8) {
            const int kr = kk + lr;
            uint32_t a[4][4], b[4][2];
            #pragma unroll
            for (int mi = 0; mi < 4; mi++) {
                int m = m0 + mi * 16 + lq;
                a[mi][0] = __float_as_uint(sA[(size_t)m       * MMA_LD + kr]);
                a[mi][1] = __float_as_uint(sA[(size_t)(m + 8) * MMA_LD + kr]);
                a[mi][2] = __float_as_uint(sA[(size_t)m       * MMA_LD + kr + 4]);
                a[mi][3] = __float_as_uint(sA[(size_t)(m + 8) * MMA_LD + kr + 4]);
            }
            #pragma unroll
            for (int ni = 0; ni < 4; ni++) {
                int n = n0 + ni * 8 + lq;
                b[ni][0] = __float_as_uint(sB[(size_t)n * MMA_LD + kr]);
                b[ni][1] = __float_as_uint(sB[(size_t)n * MMA_LD + kr + 4]);
            }
            #pragma unroll
            for (int mi = 0; mi < 4; mi++)
                #pragma unroll
                for (int ni = 0; ni < 4; ni++)
                    mma_tf32(acc[mi][ni], a[mi], b[ni]);
        }
    }

    #pragma unroll
    for (int mi = 0; mi < 4; mi++) {
        #pragma unroll
        for (int half = 0; half < 2; half++) {
            const int r = row0 + m0 + mi * 16 + lq + half * 8;
            #pragma unroll
            for (int ni = 0; ni < 4; ni++) {
                const int c = col0 + n0 + ni * 8 + 2 * lr;
                float vx = acc[mi][ni][half * 2 + 0];
                float vy = acc[mi][ni][half * 2 + 1];
                if (EPI >= 1) { vx += bias[c]; vy += bias[c + 1]; }
                if (EPI == 2) {
                    vx = 0.5f * vx * (1.f + erff(vx * 0.70710678118654752f));
                    vy = 0.5f * vy * (1.f + erff(vy * 0.70710678118654752f));
                    vx = tf32r(vx); vy = tf32r(vy);
                }
                *(float2*)(C + (size_t)r * N + c) = make_float2(vx, vy);
            }
        }
    }
}

// ---------------- fp32 SGEMM (kqv; output tf32-rounded) --------------------
template<int BM,int BN,int BK,int TM,int TN>
__global__ __launch_bounds__((BM/TM)*(BN/TN))
void gemm_kernel(const float* __restrict__ A, const float* __restrict__ W,
                 float* __restrict__ C, int M, int N, int K)
{
    constexpr int THREADS = (BM/TM)*(BN/TN);
    __shared__ float As[BK][BM];
    __shared__ float Bs[BK][BN];
    const int tid = threadIdx.x;
    const int tx  = tid % (BN/TN);
    const int ty  = tid / (BN/TN);
    const int row0 = blockIdx.y * BM;
    const int col0 = blockIdx.x * BN;

    float acc[TM][TN];
    #pragma unroll
    for (int i = 0; i < TM; i++)
        #pragma unroll
        for (int j = 0; j < TN; j++) acc[i][j] = 0.f;

    constexpr int AL = BM*BK/(THREADS*4);
    constexpr int BL = BK*BN/(THREADS*4);

    for (int k0 = 0; k0 < K; k0 += BK) {
        #pragma unroll
        for (int i = 0; i < AL; i++) {
            int e = tid + i*THREADS;
            int r = e / (BK/4);
            int kq = e % (BK/4);
            float4 v = *(const float4*)(A + (size_t)(row0 + r)*K + k0 + kq*4);
            As[kq*4+0][r] = v.x; As[kq*4+1][r] = v.y;
            As[kq*4+2][r] = v.z; As[kq*4+3][r] = v.w;
        }
        #pragma unroll
        for (int i = 0; i < BL; i++) {
            int e = tid + i*THREADS;
            int r  = e / (BN/4);
            int cq = e % (BN/4);
            *(float4*)&Bs[r][cq*4] =
                *(const float4*)(W + (size_t)(k0 + r)*N + col0 + cq*4);
        }
        __syncthreads();
        #pragma unroll
        for (int kk = 0; kk < BK; kk++) {
            float a[TM], b[TN];
            #pragma unroll
            for (int i = 0; i < TM; i += 4) {
                float4 t = *(const float4*)&As[kk][ty*TM + i];
                a[i] = t.x; a[i+1] = t.y; a[i+2] = t.z; a[i+3] = t.w;
            }
            #pragma unroll
            for (int j = 0; j < TN; j += 4) {
                float4 t = *(const float4*)&Bs[kk][tx*TN + j];
                b[j] = t.x; b[j+1] = t.y; b[j+2] = t.z; b[j+3] = t.w;
            }
            #pragma unroll
            for (int i = 0; i < TM; i++)
                #pragma unroll
                for (int j = 0; j < TN; j++)
                    acc[i][j] += a[i]*b[j];
        }
        __syncthreads();
    }
    #pragma unroll
    for (int i = 0; i < TM; i++) {
        int r = row0 + ty*TM + i;
        #pragma unroll
        for (int j = 0; j < TN; j += 4) {
            int c = col0 + tx*TN + j;
            float4 v = make_float4(tf32r(acc[i][j]),   tf32r(acc[i][j+1]),
                                   tf32r(acc[i][j+2]), tf32r(acc[i][j+3]));
            *(float4*)(C + (size_t)r*N + c) = v;
        }
    }
}

// ---------------- tensor-core flash attention -------------------------------
// grid (B*H, T/128), 256 threads = 8 warps, each warp 16 q-rows x 64 keys.
// kqv pre-rounded to tf32. Output tf32-rounded.
#define KLD 68
#define VLD 72
#define ATTN_SMEM ((128*KLD + 2*64*KLD + 2*64*VLD + 128*KLD)*(int)sizeof(float))

__global__ __launch_bounds__(256)
void attn_mma(const float* __restrict__ kqv, float* __restrict__ res)
{
    extern __shared__ float sm[];
    float* Qs = sm;                       // 128 x KLD
    float* Ks = Qs + 128*KLD;             // 2 x 64 x KLD
    float* Vs = Ks + 2*64*KLD;            // 2 x 64 x VLD
    float* Ps = Vs + 2*64*VLD;            // 128 x KLD

    const int bh = blockIdx.x;
    const int b  = bh >> 4;
    const int h  = bh & 15;
    const int q0 = blockIdx.y * 128;
    const int tid  = threadIdx.x;
    const int lane = tid & 31;
    const int wid  = tid >> 5;
    const int lq = lane >> 2, lr = lane & 3;
    const int m0 = wid * 16;
    const size_t rstr = (size_t)Hh * 3 * Ss;      // 3072
    const float* base = kqv + (size_t)(b * Tt) * rstr + h * 192;

    const uint32_t ks_u = smem_u32(Ks);
    const uint32_t vs_u = smem_u32(Vs);

    // load Q tile (q at col offset 64)
    #pragma unroll
    for (int i = 0; i < 8; i++) {
        int e = tid + i * 256;
        int r = e >> 4, c4 = e & 15;
        float4 v = *(const float4*)(base + (size_t)(q0 + r) * rstr + 64 + c4 * 4);
        float* d = Qs + r * KLD + c4 * 4;
        d[0] = v.x; d[1] = v.y; d[2] = v.z; d[3] = v.w;
    }

    auto issue_kv = [&](int kt, int s) {
        const float* kb = base + (size_t)(kt * 64) * rstr;
        #pragma unroll
        for (int i = 0; i < 4; i++) {
            int e = tid + i * 256;
            int r = e >> 4, c4 = e & 15;
            cpa16(ks_u + (uint32_t)((s * 64 + r) * KLD + c4 * 4) * 4,
                  kb + (size_t)r * rstr + c4 * 4);
            cpa16(vs_u + (uint32_t)((s * 64 + r) * VLD + c4 * 4) * 4,
                  kb + (size_t)r * rstr + 128 + c4 * 4);
        }
        asm volatile("cp.async.commit_group;" ::: "memory");
    };

    issue_kv(0, 0);
    __syncthreads();   // Q tile visible to all warps

    // hoist Q fragments (constant across key tiles)
    uint32_t qf[8][4];
    #pragma unroll
    for (int kk = 0; kk < 8; kk++) {
        int kc = kk * 8 + lr;
        qf[kk][0] = __float_as_uint(Qs[(m0 + lq)     * KLD + kc]);
        qf[kk][1] = __float_as_uint(Qs[(m0 + lq + 8) * KLD + kc]);
        qf[kk][2] = __float_as_uint(Qs[(m0 + lq)     * KLD + kc + 4]);
        qf[kk][3] = __float_as_uint(Qs[(m0 + lq + 8) * KLD + kc + 4]);
    }

    float mrow[2] = { -1e30f, -1e30f };
    float lrow[2] = { 0.f, 0.f };
    float acc_o[8][4];
    #pragma unroll
    for (int nf = 0; nf < 8; nf++)
        #pragma unroll
        for (int c = 0; c < 4; c++) acc_o[nf][c] = 0.f;

    const int NT = Tt / 64;
    for (int kt = 0; kt < NT; kt++) {
        const int s = kt & 1;
        if (kt + 1 < NT) {
            issue_kv(kt + 1, s ^ 1);
            asm volatile("cp.async.wait_group 1;" ::: "memory");
        } else {
            asm volatile("cp.async.wait_group 0;" ::: "memory");
        }
        __syncthreads();

        const float* K0 = Ks + s * 64 * KLD;
        const float* V0 = Vs + s * 64 * VLD;

        // S = Q @ K^T (scaled later)
        float acc_s[8][4];
        #pragma unroll
        for (int nf = 0; nf < 8; nf++)
            #pragma unroll
            for (int c = 0; c < 4; c++) acc_s[nf][c] = 0.f;

        #pragma unroll
        for (int kk = 0; kk < 8; kk++) {
            int kc = kk * 8 + lr;
            #pragma unroll
            for (int nf = 0; nf < 8; nf++) {
                uint32_t bfr[2];
                bfr[0] = __float_as_uint(K0[(nf * 8 + lq) * KLD + kc]);
                bfr[1] = __float_as_uint(K0[(nf * 8 + lq) * KLD + kc + 4]);
                mma_tf32(acc_s[nf], qf[kk], bfr);
            }
        }

        // online softmax (rows lq / lq+8; reduce over quad lanes)
        #pragma unroll
        for (int nf = 0; nf < 8; nf++)
            #pragma unroll
            for (int c = 0; c < 4; c++) acc_s[nf][c] *= 0.125f;

        #pragma unroll
        for (int hh = 0; hh < 2; hh++) {
            float rmax = -1e30f;
            #pragma unroll
            for (int nf = 0; nf < 8; nf++)
                rmax = fmaxf(rmax, fmaxf(acc_s[nf][2*hh], acc_s[nf][2*hh+1]));
            rmax = fmaxf(rmax, __shfl_xor_sync(0xffffffffu, rmax, 1));
            rmax = fmaxf(rmax, __shfl_xor_sync(0xffffffffu, rmax, 2));
            float mn = fmaxf(mrow[hh], rmax);
            float scale = __expf(mrow[hh] - mn);
            float rs = 0.f;
            #pragma unroll
            for (int nf = 0; nf < 8; nf++) {
                float p0 = tf32r(__expf(acc_s[nf][2*hh]   - mn));
                float p1 = tf32r(__expf(acc_s[nf][2*hh+1] - mn));
                rs += p0 + p1;
                *(float2*)&Ps[(m0 + lq + 8*hh) * KLD + nf * 8 + 2 * lr] =
                    make_float2(p0, p1);
            }
            rs += __shfl_xor_sync(0xffffffffu, rs, 1);
            rs += __shfl_xor_sync(0xffffffffu, rs, 2);
            lrow[hh] = lrow[hh] * scale + rs;
            mrow[hh] = mn;
            #pragma unroll
            for (int nf = 0; nf < 8; nf++) {
                acc_o[nf][2*hh]   *= scale;
                acc_o[nf][2*hh+1] *= scale;
            }
        }
        __syncwarp();

        // O += P @ V
        #pragma unroll
        for (int kk = 0; kk < 8; kk++) {
            int kc = kk * 8 + lr;
            uint32_t a[4];
            a[0] = __float_as_uint(Ps[(m0 + lq)     * KLD + kc]);
            a[1] = __float_as_uint(Ps[(m0 + lq + 8) * KLD + kc]);
            a[2] = __float_as_uint(Ps[(m0 + lq)     * KLD + kc + 4]);
            a[3] = __float_as_uint(Ps[(m0 + lq + 8) * KLD + kc + 4]);
            #pragma unroll
            for (int nf = 0; nf < 8; nf++) {
                uint32_t bfr[2];
                bfr[0] = __float_as_uint(V0[(kc)     * VLD + nf * 8 + lq]);
                bfr[1] = __float_as_uint(V0[(kc + 4) * VLD + nf * 8 + lq]);
                mma_tf32(acc_o[nf], a, bfr);
            }
        }
        __syncthreads();   // protect K/V buffers for next issue
    }

    // epilogue: normalize, round, store
    #pragma unroll
    for (int hh = 0; hh < 2; hh++) {
        float inv = 1.f / lrow[hh];
        int row = q0 + m0 + lq + 8 * hh;
        float* orow = res + (size_t)(b * Tt + row) * EMBv + h * 64;
        #pragma unroll
        for (int nf = 0; nf < 8; nf++) {
            float2 v = make_float2(tf32r(acc_o[nf][2*hh]   * inv),
                                   tf32r(acc_o[nf][2*hh+1] * inv));
            *(float2*)(orow + nf * 8 + 2 * lr) = v;
        }
    }
}

// ---------------- fused residual add + LayerNorm ---------------------------
__global__ __launch_bounds__(256)
void add_ln_kernel(const float* __restrict__ xa, const float* __restrict__ xb,
                   const float* __restrict__ g, const float* __restrict__ bt,
                   float* __restrict__ out, float* __restrict__ out_r)
{
    const int row = blockIdx.x;
    const int tid = threadIdx.x;
    const float* pa = xa + (size_t)row*EMBv;
    const float* pb = xb + (size_t)row*EMBv;
    float v[4], s = 0.f, s2 = 0.f;
    #pragma unroll
    for (int i = 0; i < 4; i++) {
        int c = tid + i*256;
        v[i] = pa[c] + pb[c];
        s += v[i]; s2 += v[i]*v[i];
    }
    #pragma unroll
    for (int off = 16; off > 0; off >>= 1) {
        s  += __shfl_xor_sync(0xffffffffu, s,  off);
        s2 += __shfl_xor_sync(0xffffffffu, s2, off);
    }
    __shared__ float rs[8], rs2[8];
    int w = tid >> 5, lane = tid & 31;
    if (lane == 0) { rs[w] = s; rs2[w] = s2; }
    __syncthreads();
    if (w == 0) {
        float a  = (lane < 8) ? rs[lane]  : 0.f;
        float a2 = (lane < 8) ? rs2[lane] : 0.f;
        #pragma unroll
        for (int off = 4; off > 0; off >>= 1) {
            a  += __shfl_xor_sync(0xffffffffu, a,  off);
            a2 += __shfl_xor_sync(0xffffffffu, a2, off);
        }
        if (lane == 0) { rs[0] = a; rs2[0] = a2; }
    }
    __syncthreads();
    float mean = rs[0] * (1.f/EMBv);
    float var  = rs2[0] * (1.f/EMBv) - mean*mean;
    float inv  = rsqrtf(var + 1e-5f);
    #pragma unroll
    for (int i = 0; i < 4; i++) {
        int c = tid + i*256;
        float o = (v[i] - mean)*inv*g[c] + bt[c];
        out[(size_t)row*EMBv + c] = o;
        if (out_r) out_r[(size_t)row*EMBv + c] = tf32r(o);
    }
}

// ---------------- launch ----------------------------------------------------
extern "C" void kernel_launch(void* const* d_in, const int* in_sizes, int n_in,
                              void* d_out, int out_size)
{
    const float* x     = (const float*)d_in[0];
    const float* Wkqv  = (const float*)d_in[1];
    const float* Wproj = (const float*)d_in[2];
    const float* g1    = (const float*)d_in[3];
    const float* b1    = (const float*)d_in[4];
    const float* W1    = (const float*)d_in[5];
    const float* bff1  = (const float*)d_in[6];
    const float* W2    = (const float*)d_in[7];
    const float* bff2  = (const float*)d_in[8];
    const float* g2    = (const float*)d_in[9];
    const float* b2    = (const float*)d_in[10];
    float* out = (float*)d_out;

    float *kqv, *res, *mha, *x1, *x1r, *hbuf, *ff, *wtp, *wt1, *wt2;
    cudaGetSymbolAddress((void**)&kqv,  g_kqv);
    cudaGetSymbolAddress((void**)&res,  g_res);
    cudaGetSymbolAddress((void**)&mha,  g_mha);
    cudaGetSymbolAddress((void**)&x1,   g_x1);
    cudaGetSymbolAddress((void**)&x1r,  g_x1r);
    cudaGetSymbolAddress((void**)&hbuf, g_h);
    cudaGetSymbolAddress((void**)&ff,   g_ff);
    cudaGetSymbolAddress((void**)&wtp,  g_wtp);
    cudaGetSymbolAddress((void**)&wt1,  g_wt1);
    cudaGetSymbolAddress((void**)&wt2,  g_wt2);

    cudaFuncSetAttribute(mma_gemm<0>, cudaFuncAttributeMaxDynamicSharedMemorySize, MMA_SMEM);
    cudaFuncSetAttribute(mma_gemm<1>, cudaFuncAttributeMaxDynamicSharedMemorySize, MMA_SMEM);
    cudaFuncSetAttribute(mma_gemm<2>, cudaFuncAttributeMaxDynamicSharedMemorySize, MMA_SMEM);
    cudaFuncSetAttribute(attn_mma,    cudaFuncAttributeMaxDynamicSharedMemorySize, ATTN_SMEM);

    // 0) transpose + tf32-round weights to [N,K]
    transpose_kernel<<<dim3(EMBv/32, EMBv/32), dim3(32,8)>>>(Wproj, wtp, EMBv, EMBv);
    transpose_kernel<<<dim3(FF/32,   EMBv/32), dim3(32,8)>>>(W1,    wt1, EMBv, FF);
    transpose_kernel<<<dim3(EMBv/32, FF/32),   dim3(32,8)>>>(W2,    wt2, FF,   EMBv);

    // 1) kqv = reshape(x,[B*T*H,64]) @ Wkqv[64,192]  (fp32; tf32-rounded out)
    gemm_kernel<128,64,16,8,4><<<dim3(3, (NTOK*Hh)/128), 256>>>(
        x, Wkqv, kqv, NTOK*Hh, 3*Ss, Ss);

    // 2) attention -> res (tf32 mma flash attention)
    attn_mma<<<dim3(Bb*Hh, Tt/128), 256, ATTN_SMEM>>>(kqv, res);

    // 3) mha = res @ Wproj            (tf32 mma.sync)
    mma_gemm<0><<<dim3(EMBv/128, NTOK/128), 256, MMA_SMEM>>>(
        res, wtp, nullptr, mha, NTOK, EMBv, EMBv);

    // 4) x1 = LN(x + mha)  (+rounded copy x1r)
    add_ln_kernel<<<NTOK, 256>>>(x, mha, g1, b1, x1, x1r);

    // 5) h = gelu(x1 @ W1 + bff1)     (tf32 mma.sync; rounded output)
    mma_gemm<2><<<dim3(FF/128, NTOK/128), 256, MMA_SMEM>>>(
        x1r, wt1, bff1, hbuf, NTOK, FF, EMBv);

    // 6) ff = h @ W2 + bff2           (tf32 mma.sync)
    mma_gemm<1><<<dim3(EMBv/128, NTOK/128), 256, MMA_SMEM>>>(
        hbuf, wt2, bff2, ff, NTOK, EMBv, FF);

    // 7) out = LN(x1 + ff)
    add_ln_kernel<<<NTOK, 256>>>(x1, ff, g2, b2, out, nullptr);
}

// round 5
// speedup vs baseline: 5.5782x; 1.8093x over previous
#include <cuda_runtime.h>
#include <cuda_fp16.h>
#include <math.h>
#include <stdint.h>

#define Bb   2
#define Tt   2048
#define Hh   16
#define Ss   64
#define EMBv 1024
#define NTOK (Bb*Tt)      // 4096 tokens
#define FF   (4*EMBv)     // 4096

// ---------------- scratch (static device globals) ---------------------------
__device__ __half g_kqv[NTOK*Hh*3*Ss]; // [B,T,H,192] k|q|v (fp16)
__device__ __half g_res[NTOK*EMBv];    // attention output (fp16)
__device__ float  g_mha[NTOK*EMBv];    // proj output (fp32)
__device__ float  g_x1 [NTOK*EMBv];    // after first LN (fp32, exact)
__device__ __half g_x1r[NTOK*EMBv];    // after first LN (fp16 copy)
__device__ __half g_h  [NTOK*FF];      // gelu(...) (fp16)
__device__ float  g_ff [NTOK*EMBv];    // h @ W2 + b (fp32)
__device__ __half g_wtp[EMBv*EMBv];    // Wproj^T [N,K] fp16
__device__ __half g_wt1[EMBv*FF];      // W1^T fp16
__device__ __half g_wt2[FF*EMBv];      // W2^T fp16

// ======================= helpers ===========================================
__device__ __forceinline__ uint32_t smem_u32(const void* p) {
    uint32_t a;
    asm("{ .reg .u64 t; cvta.to.shared.u64 t, %1; cvt.u32.u64 %0, t; }"
        : "=r"(a) : "l"(p));
    return a;
}
__device__ __forceinline__ void cpa16(uint32_t s, const void* g) {
    asm volatile("cp.async.cg.shared.global [%0], [%1], 16;\n" :: "r"(s), "l"(g));
}
__device__ __forceinline__ void mma_f16(float* c, const uint32_t* a, const uint32_t* b) {
    asm volatile(
        "mma.sync.aligned.m16n8k16.row.col.f32.f16.f16.f32 "
        "{%0,%1,%2,%3}, {%4,%5,%6,%7}, {%8,%9}, {%0,%1,%2,%3};"
        : "+f"(c[0]), "+f"(c[1]), "+f"(c[2]), "+f"(c[3])
        : "r"(a[0]), "r"(a[1]), "r"(a[2]), "r"(a[3]), "r"(b[0]), "r"(b[1]));
}
__device__ __forceinline__ void ldsm_x2_trans(uint32_t& r0, uint32_t& r1, uint32_t addr) {
    asm volatile("ldmatrix.sync.aligned.m8n8.x2.trans.shared.b16 {%0,%1}, [%2];"
                 : "=r"(r0), "=r"(r1) : "r"(addr));
}

// ======================= weight transpose + fp16 ===========================
__global__ __launch_bounds__(256)
void transpose_kernel(const float* __restrict__ in, __half* __restrict__ out,
                      int R, int C)
{
    __shared__ float t[32][33];
    const int tx = threadIdx.x, ty = threadIdx.y;
    const int c = blockIdx.x * 32 + tx;
    const int r0 = blockIdx.y * 32;
    #pragma unroll
    for (int i = 0; i < 32; i += 8)
        t[ty + i][tx] = in[(size_t)(r0 + ty + i) * C + c];
    __syncthreads();
    const int oc = blockIdx.y * 32 + tx;
    const int or0 = blockIdx.x * 32;
    #pragma unroll
    for (int i = 0; i < 32; i += 8)
        out[(size_t)(or0 + ty + i) * R + oc] = __float2half_rn(t[tx][ty + i]);
}

// ======================= fp16 mma.sync GEMM ================================
// C[M,N] = epi(A[M,K] @ Bt[N,K]^T + bias). CTA 128x256, BK=64, 8 warps 64x64.
// EPI: 0 none, 1 +bias, 2 +bias+GELU. A/Bt fp16, accum fp32, OutT output.
#define GLD     72                         // halves per smem row (64 + 8 pad)
#define STAGEH  ((128+256)*GLD)            // halves per stage
#define MMA_SMEM (3*STAGEH*(int)sizeof(__half))   // 165888 B

template<int EPI, typename OutT>
__global__ __launch_bounds__(256, 1)
void mma_gemm(const __half* __restrict__ A, const __half* __restrict__ Bt,
              const float* __restrict__ bias, OutT* __restrict__ C,
              int M, int N, int K)
{
    extern __shared__ __half smh[];
    const int tid  = threadIdx.x;
    const int lane = tid & 31;
    const int wid  = tid >> 5;
    const int m0 = (wid & 1) * 64;
    const int n0 = (wid >> 1) * 64;
    const int row0 = blockIdx.y * 128;
    const int col0 = blockIdx.x * 256;
    const int lq = lane >> 2;
    const int lr = lane & 3;

    float acc[4][8][4];
    #pragma unroll
    for (int i = 0; i < 4; i++)
        #pragma unroll
        for (int j = 0; j < 8; j++)
            #pragma unroll
            for (int k = 0; k < 4; k++) acc[i][j][k] = 0.f;

    auto issue = [&](int kt, int s) {
        const int k0 = kt * 64;
        __half* dstA = smh + s * STAGEH;
        __half* dstB = dstA + 128 * GLD;
        #pragma unroll
        for (int i = 0; i < 4; i++) {               // A: 128 rows x 8 chunks
            int e = tid + i * 256;
            int r = e >> 3, c8 = e & 7;
            cpa16(smem_u32(dstA + r * GLD + c8 * 8),
                  A + (size_t)(row0 + r) * K + k0 + c8 * 8);
        }
        #pragma unroll
        for (int i = 0; i < 8; i++) {               // B: 256 rows x 8 chunks
            int e = tid + i * 256;
            int r = e >> 3, c8 = e & 7;
            cpa16(smem_u32(dstB + r * GLD + c8 * 8),
                  Bt + (size_t)(col0 + r) * K + k0 + c8 * 8);
        }
        asm volatile("cp.async.commit_group;" ::: "memory");
    };

    const int NK = K / 64;
    issue(0, 0);
    issue(1, 1);

    for (int kt = 0; kt < NK; kt++) {
        const int s = kt % 3;
        if (kt == NK - 1) asm volatile("cp.async.wait_group 0;" ::: "memory");
        else              asm volatile("cp.async.wait_group 1;" ::: "memory");
        __syncthreads();
        if (kt + 2 < NK) issue(kt + 2, (kt + 2) % 3);

        const __half* sA = smh + s * STAGEH;
        const __half* sB = sA + 128 * GLD;

        #pragma unroll
        for (int ks = 0; ks < 4; ks++) {
            const int kh = ks * 16 + 2 * lr;
            uint32_t a[4][4], b[8][2];
            #pragma unroll
            for (int mi = 0; mi < 4; mi++) {
                const __half* pr = sA + (size_t)(m0 + mi * 16 + lq) * GLD + kh;
                a[mi][0] = *(const uint32_t*)(pr);
                a[mi][1] = *(const uint32_t*)(pr + 8 * GLD);
                a[mi][2] = *(const uint32_t*)(pr + 8);
                a[mi][3] = *(const uint32_t*)(pr + 8 * GLD + 8);
            }
            #pragma unroll
            for (int ni = 0; ni < 8; ni++) {
                const __half* pr = sB + (size_t)(n0 + ni * 8 + lq) * GLD + kh;
                b[ni][0] = *(const uint32_t*)(pr);
                b[ni][1] = *(const uint32_t*)(pr + 8);
            }
            #pragma unroll
            for (int mi = 0; mi < 4; mi++)
                #pragma unroll
                for (int ni = 0; ni < 8; ni++)
                    mma_f16(acc[mi][ni], a[mi], b[ni]);
        }
    }

    #pragma unroll
    for (int mi = 0; mi < 4; mi++) {
        #pragma unroll
        for (int hh = 0; hh < 2; hh++) {
            const int r = row0 + m0 + mi * 16 + lq + hh * 8;
            #pragma unroll
            for (int ni = 0; ni < 8; ni++) {
                const int c = col0 + n0 + ni * 8 + 2 * lr;
                float vx = acc[mi][ni][hh * 2 + 0];
                float vy = acc[mi][ni][hh * 2 + 1];
                if (EPI >= 1) { vx += bias[c]; vy += bias[c + 1]; }
                if (EPI == 2) {
                    vx = 0.5f * vx * (1.f + erff(vx * 0.70710678118654752f));
                    vy = 0.5f * vy * (1.f + erff(vy * 0.70710678118654752f));
                }
                if (sizeof(OutT) == 2) {
                    *(__half2*)((__half*)C + (size_t)r * N + c) =
                        __floats2half2_rn(vx, vy);
                } else {
                    *(float2*)((float*)C + (size_t)r * N + c) = make_float2(vx, vy);
                }
            }
        }
    }
}

// ---------------- fp32 SGEMM (kqv; fp16 output) ----------------------------
template<int BM,int BN,int BK,int TM,int TN>
__global__ __launch_bounds__((BM/TM)*(BN/TN))
void gemm_kernel(const float* __restrict__ A, const float* __restrict__ W,
                 __half* __restrict__ C, int M, int N, int K)
{
    constexpr int THREADS = (BM/TM)*(BN/TN);
    __shared__ float As[BK][BM];
    __shared__ float Bs[BK][BN];
    const int tid = threadIdx.x;
    const int tx  = tid % (BN/TN);
    const int ty  = tid / (BN/TN);
    const int row0 = blockIdx.y * BM;
    const int col0 = blockIdx.x * BN;

    float acc[TM][TN];
    #pragma unroll
    for (int i = 0; i < TM; i++)
        #pragma unroll
        for (int j = 0; j < TN; j++) acc[i][j] = 0.f;

    constexpr int AL = BM*BK/(THREADS*4);
    constexpr int BL = BK*BN/(THREADS*4);

    for (int k0 = 0; k0 < K; k0 += BK) {
        #pragma unroll
        for (int i = 0; i < AL; i++) {
            int e = tid + i*THREADS;
            int r = e / (BK/4);
            int kq = e % (BK/4);
            float4 v = *(const float4*)(A + (size_t)(row0 + r)*K + k0 + kq*4);
            As[kq*4+0][r] = v.x; As[kq*4+1][r] = v.y;
            As[kq*4+2][r] = v.z; As[kq*4+3][r] = v.w;
        }
        #pragma unroll
        for (int i = 0; i < BL; i++) {
            int e = tid + i*THREADS;
            int r  = e / (BN/4);
            int cq = e % (BN/4);
            *(float4*)&Bs[r][cq*4] =
                *(const float4*)(W + (size_t)(k0 + r)*N + col0 + cq*4);
        }
        __syncthreads();
        #pragma unroll
        for (int kk = 0; kk < BK; kk++) {
            float a[TM], b[TN];
            #pragma unroll
            for (int i = 0; i < TM; i += 4) {
                float4 t = *(const float4*)&As[kk][ty*TM + i];
                a[i] = t.x; a[i+1] = t.y; a[i+2] = t.z; a[i+3] = t.w;
            }
            #pragma unroll
            for (int j = 0; j < TN; j += 4) {
                float4 t = *(const float4*)&Bs[kk][tx*TN + j];
                b[j] = t.x; b[j+1] = t.y; b[j+2] = t.z; b[j+3] = t.w;
            }
            #pragma unroll
            for (int i = 0; i < TM; i++)
                #pragma unroll
                for (int j = 0; j < TN; j++)
                    acc[i][j] += a[i]*b[j];
        }
        __syncthreads();
    }
    #pragma unroll
    for (int i = 0; i < TM; i++) {
        int r = row0 + ty*TM + i;
        #pragma unroll
        for (int j = 0; j < TN; j += 2) {
            int c = col0 + tx*TN + j;
            *(__half2*)(C + (size_t)r*N + c) =
                __floats2half2_rn(acc[i][j], acc[i][j+1]);
        }
    }
}

// ---------------- fp16 tensor-core flash attention --------------------------
// grid (B*H, T/128), 256 threads = 8 warps, each warp 16 q-rows x 64 keys.
#define ALD 72                                   // halves per row
#define ATTN_SMEM ((128*ALD + 2*64*ALD + 2*64*ALD + 128*ALD)*(int)sizeof(__half))

__global__ __launch_bounds__(256, 2)
void attn_mma(const __half* __restrict__ kqv, __half* __restrict__ res)
{
    extern __shared__ __half sma[];
    __half* Qs = sma;                     // 128 x ALD
    __half* Ks = Qs + 128*ALD;            // 2 x 64 x ALD
    __half* Vs = Ks + 2*64*ALD;           // 2 x 64 x ALD  [key][dim]
    __half* Ps = Vs + 2*64*ALD;           // 128 x ALD

    const int bh = blockIdx.x;
    const int b  = bh >> 4;
    const int h  = bh & 15;
    const int q0 = blockIdx.y * 128;
    const int tid  = threadIdx.x;
    const int lane = tid & 31;
    const int wid  = tid >> 5;
    const int lq = lane >> 2, lr = lane & 3;
    const int m0 = wid * 16;
    const size_t rstr = (size_t)Hh * 3 * Ss;      // 3072 halves
    const __half* base = kqv + (size_t)(b * Tt) * rstr + h * 192;

    const uint32_t ks_u = smem_u32(Ks);
    const uint32_t vs_u = smem_u32(Vs);
    const uint32_t qs_u = smem_u32(Qs);

    // load Q tile (q at half-offset 64): 128 rows x 8 chunks of 16B
    #pragma unroll
    for (int i = 0; i < 4; i++) {
        int e = tid + i * 256;
        int r = e >> 3, c8 = e & 7;
        cpa16(qs_u + (uint32_t)(r * ALD + c8 * 8) * 2,
              base + (size_t)(q0 + r) * rstr + 64 + c8 * 8);
    }
    asm volatile("cp.async.commit_group;" ::: "memory");

    auto issue_kv = [&](int kt, int s) {
        const __half* kb = base + (size_t)(kt * 64) * rstr;
        #pragma unroll
        for (int i = 0; i < 2; i++) {
            int e = tid + i * 256;
            int r = e >> 3, c8 = e & 7;
            cpa16(ks_u + (uint32_t)((s * 64 + r) * ALD + c8 * 8) * 2,
                  kb + (size_t)r * rstr + c8 * 8);
            cpa16(vs_u + (uint32_t)((s * 64 + r) * ALD + c8 * 8) * 2,
                  kb + (size_t)r * rstr + 128 + c8 * 8);
        }
        asm volatile("cp.async.commit_group;" ::: "memory");
    };

    issue_kv(0, 0);
    asm volatile("cp.async.wait_group 1;" ::: "memory");   // Q done
    __syncthreads();

    // hoist Q fragments (4 k16 steps x 4 regs)
    uint32_t qf[4][4];
    #pragma unroll
    for (int ks = 0; ks < 4; ks++) {
        const __half* pr = Qs + (size_t)(m0 + lq) * ALD + ks * 16 + 2 * lr;
        qf[ks][0] = *(const uint32_t*)(pr);
        qf[ks][1] = *(const uint32_t*)(pr + 8 * ALD);
        qf[ks][2] = *(const uint32_t*)(pr + 8);
        qf[ks][3] = *(const uint32_t*)(pr + 8 * ALD + 8);
    }

    float mrow[2] = { -1e30f, -1e30f };
    float lrow[2] = { 0.f, 0.f };
    float acc_o[8][4];
    #pragma unroll
    for (int nf = 0; nf < 8; nf++)
        #pragma unroll
        for (int c = 0; c < 4; c++) acc_o[nf][c] = 0.f;

    const int NT = Tt / 64;
    for (int kt = 0; kt < NT; kt++) {
        const int s = kt & 1;
        if (kt + 1 < NT) {
            issue_kv(kt + 1, s ^ 1);
            asm volatile("cp.async.wait_group 1;" ::: "memory");
        } else {
            asm volatile("cp.async.wait_group 0;" ::: "memory");
        }
        __syncthreads();

        const __half* K0 = Ks + s * 64 * ALD;

        // S = Q @ K^T
        float acc_s[8][4];
        #pragma unroll
        for (int nf = 0; nf < 8; nf++)
            #pragma unroll
            for (int c = 0; c < 4; c++) acc_s[nf][c] = 0.f;

        #pragma unroll
        for (int ks = 0; ks < 4; ks++) {
            const int kh = ks * 16 + 2 * lr;
            #pragma unroll
            for (int nf = 0; nf < 8; nf++) {
                const __half* pr = K0 + (size_t)(nf * 8 + lq) * ALD + kh;
                uint32_t bfr[2];
                bfr[0] = *(const uint32_t*)(pr);
                bfr[1] = *(const uint32_t*)(pr + 8);
                mma_f16(acc_s[nf], qf[ks], bfr);
            }
        }

        #pragma unroll
        for (int nf = 0; nf < 8; nf++)
            #pragma unroll
            for (int c = 0; c < 4; c++) acc_s[nf][c] *= 0.125f;

        // online softmax; write P (fp16) for PV
        #pragma unroll
        for (int hh = 0; hh < 2; hh++) {
            float rmax = -1e30f;
            #pragma unroll
            for (int nf = 0; nf < 8; nf++)
                rmax = fmaxf(rmax, fmaxf(acc_s[nf][2*hh], acc_s[nf][2*hh+1]));
            rmax = fmaxf(rmax, __shfl_xor_sync(0xffffffffu, rmax, 1));
            rmax = fmaxf(rmax, __shfl_xor_sync(0xffffffffu, rmax, 2));
            float mn = fmaxf(mrow[hh], rmax);
            float scale = __expf(mrow[hh] - mn);
            float rs = 0.f;
            #pragma unroll
            for (int nf = 0; nf < 8; nf++) {
                __half h0 = __float2half_rn(__expf(acc_s[nf][2*hh]   - mn));
                __half h1 = __float2half_rn(__expf(acc_s[nf][2*hh+1] - mn));
                rs += __half2float(h0) + __half2float(h1);
                *(__half2*)&Ps[(size_t)(m0 + lq + 8*hh) * ALD + nf * 8 + 2 * lr] =
                    __halves2half2(h0, h1);
            }
            rs += __shfl_xor_sync(0xffffffffu, rs, 1);
            rs += __shfl_xor_sync(0xffffffffu, rs, 2);
            lrow[hh] = lrow[hh] * scale + rs;
            mrow[hh] = mn;
            #pragma unroll
            for (int nf = 0; nf < 8; nf++) {
                acc_o[nf][2*hh]   *= scale;
                acc_o[nf][2*hh+1] *= scale;
            }
        }
        __syncwarp();

        // O += P @ V  (V via ldmatrix.trans)
        const uint32_t v0_u = vs_u + (uint32_t)(s * 64 * ALD) * 2;
        #pragma unroll
        for (int ks = 0; ks < 4; ks++) {
            const int kh = ks * 16 + 2 * lr;
            const __half* pp = Ps + (size_t)(m0 + lq) * ALD + kh;
            uint32_t a[4];
            a[0] = *(const uint32_t*)(pp);
            a[1] = *(const uint32_t*)(pp + 8 * ALD);
            a[2] = *(const uint32_t*)(pp + 8);
            a[3] = *(const uint32_t*)(pp + 8 * ALD + 8);
            const uint32_t rowaddr = v0_u +
                (uint32_t)((ks * 16 + (lane & 15)) * ALD) * 2;
            #pragma unroll
            for (int nf = 0; nf < 8; nf++) {
                uint32_t b0, b1;
                ldsm_x2_trans(b0, b1, rowaddr + (uint32_t)(nf * 8) * 2);
                uint32_t bfr[2] = { b0, b1 };
                mma_f16(acc_o[nf], a, bfr);
            }
        }
        __syncthreads();
    }

    // epilogue: normalize, store fp16
    #pragma unroll
    for (int hh = 0; hh < 2; hh++) {
        float inv = 1.f / lrow[hh];
        int row = q0 + m0 + lq + 8 * hh;
        __half* orow = res + (size_t)(b * Tt + row) * EMBv + h * 64;
        #pragma unroll
        for (int nf = 0; nf < 8; nf++)
            *(__half2*)(orow + nf * 8 + 2 * lr) =
                __floats2half2_rn(acc_o[nf][2*hh] * inv, acc_o[nf][2*hh+1] * inv);
    }
}

// ---------------- fused residual add + LayerNorm ---------------------------
__global__ __launch_bounds__(256)
void add_ln_kernel(const float* __restrict__ xa, const float* __restrict__ xb,
                   const float* __restrict__ g, const float* __restrict__ bt,
                   float* __restrict__ out, __half* __restrict__ out_r)
{
    const int row = blockIdx.x;
    const int tid = threadIdx.x;
    const float* pa = xa + (size_t)row*EMBv;
    const float* pb = xb + (size_t)row*EMBv;
    float v[4], s = 0.f, s2 = 0.f;
    #pragma unroll
    for (int i = 0; i < 4; i++) {
        int c = tid + i*256;
        v[i] = pa[c] + pb[c];
        s += v[i]; s2 += v[i]*v[i];
    }
    #pragma unroll
    for (int off = 16; off > 0; off >>= 1) {
        s  += __shfl_xor_sync(0xffffffffu, s,  off);
        s2 += __shfl_xor_sync(0xffffffffu, s2, off);
    }
    __shared__ float rs[8], rs2[8];
    int w = tid >> 5, lane = tid & 31;
    if (lane == 0) { rs[w] = s; rs2[w] = s2; }
    __syncthreads();
    if (w == 0) {
        float a  = (lane < 8) ? rs[lane]  : 0.f;
        float a2 = (lane < 8) ? rs2[lane] : 0.f;
        #pragma unroll
        for (int off = 4; off > 0; off >>= 1) {
            a  += __shfl_xor_sync(0xffffffffu, a,  off);
            a2 += __shfl_xor_sync(0xffffffffu, a2, off);
        }
        if (lane == 0) { rs[0] = a; rs2[0] = a2; }
    }
    __syncthreads();
    float mean = rs[0] * (1.f/EMBv);
    float var  = rs2[0] * (1.f/EMBv) - mean*mean;
    float inv  = rsqrtf(var + 1e-5f);
    #pragma unroll
    for (int i = 0; i < 4; i++) {
        int c = tid + i*256;
        float o = (v[i] - mean)*inv*g[c] + bt[c];
        out[(size_t)row*EMBv + c] = o;
        if (out_r) out_r[(size_t)row*EMBv + c] = __float2half_rn(o);
    }
}

// ---------------- launch ----------------------------------------------------
extern "C" void kernel_launch(void* const* d_in, const int* in_sizes, int n_in,
                              void* d_out, int out_size)
{
    const float* x     = (const float*)d_in[0];
    const float* Wkqv  = (const float*)d_in[1];
    const float* Wproj = (const float*)d_in[2];
    const float* g1    = (const float*)d_in[3];
    const float* b1    = (const float*)d_in[4];
    const float* W1    = (const float*)d_in[5];
    const float* bff1  = (const float*)d_in[6];
    const float* W2    = (const float*)d_in[7];
    const float* bff2  = (const float*)d_in[8];
    const float* g2    = (const float*)d_in[9];
    const float* b2    = (const float*)d_in[10];
    float* out = (float*)d_out;

    __half *kqv, *res, *x1r, *hbuf, *wtp, *wt1, *wt2;
    float  *mha, *x1, *ff;
    cudaGetSymbolAddress((void**)&kqv,  g_kqv);
    cudaGetSymbolAddress((void**)&res,  g_res);
    cudaGetSymbolAddress((void**)&mha,  g_mha);
    cudaGetSymbolAddress((void**)&x1,   g_x1);
    cudaGetSymbolAddress((void**)&x1r,  g_x1r);
    cudaGetSymbolAddress((void**)&hbuf, g_h);
    cudaGetSymbolAddress((void**)&ff,   g_ff);
    cudaGetSymbolAddress((void**)&wtp,  g_wtp);
    cudaGetSymbolAddress((void**)&wt1,  g_wt1);
    cudaGetSymbolAddress((void**)&wt2,  g_wt2);

    cudaFuncSetAttribute((const void*)mma_gemm<0,float>,
        cudaFuncAttributeMaxDynamicSharedMemorySize, MMA_SMEM);
    cudaFuncSetAttribute((const void*)mma_gemm<1,float>,
        cudaFuncAttributeMaxDynamicSharedMemorySize, MMA_SMEM);
    cudaFuncSetAttribute((const void*)mma_gemm<2,__half>,
        cudaFuncAttributeMaxDynamicSharedMemorySize, MMA_SMEM);
    cudaFuncSetAttribute((const void*)attn_mma,
        cudaFuncAttributeMaxDynamicSharedMemorySize, ATTN_SMEM);

    // 0) transpose + fp16 weights [N,K]
    transpose_kernel<<<dim3(EMBv/32, EMBv/32), dim3(32,8)>>>(Wproj, wtp, EMBv, EMBv);
    transpose_kernel<<<dim3(FF/32,   EMBv/32), dim3(32,8)>>>(W1,    wt1, EMBv, FF);
    transpose_kernel<<<dim3(EMBv/32, FF/32),   dim3(32,8)>>>(W2,    wt2, FF,   EMBv);

    // 1) kqv = reshape(x,[B*T*H,64]) @ Wkqv[64,192]  (fp32 math, fp16 out)
    gemm_kernel<128,64,16,8,4><<<dim3(3, (NTOK*Hh)/128), 256>>>(
        x, Wkqv, kqv, NTOK*Hh, 3*Ss, Ss);

    // 2) attention -> res (fp16 tensor cores)
    attn_mma<<<dim3(Bb*Hh, Tt/128), 256, ATTN_SMEM>>>(kqv, res);

    // 3) mha = res @ Wproj            (fp16 mma)
    mma_gemm<0,float><<<dim3(EMBv/256, NTOK/128), 256, MMA_SMEM>>>(
        res, wtp, nullptr, mha, NTOK, EMBv, EMBv);

    // 4) x1 = LN(x + mha)  (+fp16 copy)
    add_ln_kernel<<<NTOK, 256>>>(x, mha, g1, b1, x1, x1r);

    // 5) h = gelu(x1 @ W1 + bff1)     (fp16 mma, fp16 out)
    mma_gemm<2,__half><<<dim3(FF/256, NTOK/128), 256, MMA_SMEM>>>(
        x1r, wt1, bff1, hbuf, NTOK, FF, EMBv);

    // 6) ff = h @ W2 + bff2           (fp16 mma)
    mma_gemm<1,float><<<dim3(EMBv/256, NTOK/128), 256, MMA_SMEM>>>(
        hbuf, wt2, bff2, ff, NTOK, EMBv, FF);

    // 7) out = LN(x1 + ff)
    add_ln_kernel<<<NTOK, 256>>>(x1, ff, g2, b2, out, nullptr);
}

// round 6
// speedup vs baseline: 5.9777x; 1.0716x over previous
#include <cuda_runtime.h>
#include <cuda_fp16.h>
#include <math.h>
#include <stdint.h>

#define Bb   2
#define Tt   2048
#define Hh   16
#define Ss   64
#define EMBv 1024
#define NTOK (Bb*Tt)      // 4096 tokens
#define FF   (4*EMBv)     // 4096

// ---------------- scratch (static device globals) ---------------------------
__device__ __half g_xh [NTOK*EMBv];    // x in fp16
__device__ __half g_kqv[NTOK*Hh*3*Ss]; // [B,T,H,192] k|q|v (fp16)
__device__ __half g_res[NTOK*EMBv];    // attention output (fp16)
__device__ float  g_mha[NTOK*EMBv];    // proj output (fp32)
__device__ float  g_x1 [NTOK*EMBv];    // after first LN (fp32, exact)
__device__ __half g_x1r[NTOK*EMBv];    // after first LN (fp16 copy)
__device__ __half g_h  [NTOK*FF];      // gelu(...) (fp16)
__device__ float  g_ff [NTOK*EMBv];    // h @ W2 + b (fp32)
__device__ __half g_wqt[192*Ss];       // Wkqv^T [192,64] fp16
__device__ __half g_wtp[EMBv*EMBv];    // Wproj^T [N,K] fp16
__device__ __half g_wt1[EMBv*FF];      // W1^T fp16
__device__ __half g_wt2[FF*EMBv];      // W2^T fp16

// ======================= helpers ===========================================
__device__ __forceinline__ uint32_t smem_u32(const void* p) {
    uint32_t a;
    asm("{ .reg .u64 t; cvta.to.shared.u64 t, %1; cvt.u32.u64 %0, t; }"
        : "=r"(a) : "l"(p));
    return a;
}
__device__ __forceinline__ void cpa16(uint32_t s, const void* g) {
    asm volatile("cp.async.cg.shared.global [%0], [%1], 16;\n" :: "r"(s), "l"(g));
}
__device__ __forceinline__ void mma_f16(float* c, const uint32_t* a, const uint32_t* b) {
    asm volatile(
        "mma.sync.aligned.m16n8k16.row.col.f32.f16.f16.f32 "
        "{%0,%1,%2,%3}, {%4,%5,%6,%7}, {%8,%9}, {%0,%1,%2,%3};"
        : "+f"(c[0]), "+f"(c[1]), "+f"(c[2]), "+f"(c[3])
        : "r"(a[0]), "r"(a[1]), "r"(a[2]), "r"(a[3]), "r"(b[0]), "r"(b[1]));
}
__device__ __forceinline__ void ldsm_x4(uint32_t& r0, uint32_t& r1,
                                        uint32_t& r2, uint32_t& r3, uint32_t a) {
    asm volatile("ldmatrix.sync.aligned.m8n8.x4.shared.b16 {%0,%1,%2,%3}, [%4];"
                 : "=r"(r0), "=r"(r1), "=r"(r2), "=r"(r3) : "r"(a));
}
__device__ __forceinline__ void ldsm_x2_trans(uint32_t& r0, uint32_t& r1, uint32_t addr) {
    asm volatile("ldmatrix.sync.aligned.m8n8.x2.trans.shared.b16 {%0,%1}, [%2];"
                 : "=r"(r0), "=r"(r1) : "r"(addr));
}

// ======================= fp32 -> fp16 convert ==============================
__global__ __launch_bounds__(256)
void cvt_half_kernel(const float4* __restrict__ in, __half2* __restrict__ out, int n4)
{
    int i = blockIdx.x * 256 + threadIdx.x;
    if (i < n4) {
        float4 v = in[i];
        out[i*2+0] = __floats2half2_rn(v.x, v.y);
        out[i*2+1] = __floats2half2_rn(v.z, v.w);
    }
}

// ======================= weight transpose + fp16 ===========================
__global__ __launch_bounds__(256)
void transpose_kernel(const float* __restrict__ in, __half* __restrict__ out,
                      int R, int C)
{
    __shared__ float t[32][33];
    const int tx = threadIdx.x, ty = threadIdx.y;
    const int c = blockIdx.x * 32 + tx;
    const int r0 = blockIdx.y * 32;
    #pragma unroll
    for (int i = 0; i < 32; i += 8)
        t[ty + i][tx] = in[(size_t)(r0 + ty + i) * C + c];
    __syncthreads();
    const int oc = blockIdx.y * 32 + tx;
    const int or0 = blockIdx.x * 32;
    #pragma unroll
    for (int i = 0; i < 32; i += 8)
        out[(size_t)(or0 + ty + i) * R + oc] = __float2half_rn(t[tx][ty + i]);
}

// ======================= fp16 mma.sync GEMM (ldmatrix) ======================
// C[M,N] = epi(A[M,K] @ Bt[N,K]^T + bias). CTA 128x256, BK=64, 8 warps 64x64.
#define GLD     72
#define STAGEH  ((128+256)*GLD)
#define MMA_SMEM (3*STAGEH*(int)sizeof(__half))   // 165888 B

template<int EPI, typename OutT>
__global__ __launch_bounds__(256, 1)
void mma_gemm(const __half* __restrict__ A, const __half* __restrict__ Bt,
              const float* __restrict__ bias, OutT* __restrict__ C,
              int M, int N, int K)
{
    extern __shared__ __half smh[];
    const uint32_t smh_u = smem_u32(smh);
    const int tid  = threadIdx.x;
    const int lane = tid & 31;
    const int wid  = tid >> 5;
    const int m0 = (wid & 1) * 64;
    const int n0 = (wid >> 1) * 64;
    const int row0 = blockIdx.y * 128;
    const int col0 = blockIdx.x * 256;
    const int lq = lane >> 2;
    const int lr = lane & 3;
    const int rr = lane & 7, gg = lane >> 3;
    const int aRow = m0 + ((gg & 1) << 3) + rr;     // + mi*16
    const int aCol = (gg & 2) << 2;                 // 0|8, + ks*16
    const int bRow = n0 + ((gg >> 1) << 3) + rr;    // + ni8*16
    const int bCol = (gg & 1) << 3;                 // 0|8, + ks*16

    float acc[4][8][4];
    #pragma unroll
    for (int i = 0; i < 4; i++)
        #pragma unroll
        for (int j = 0; j < 8; j++)
            #pragma unroll
            for (int k = 0; k < 4; k++) acc[i][j][k] = 0.f;

    auto issue = [&](int kt, int s) {
        const int k0 = kt * 64;
        __half* dstA = smh + s * STAGEH;
        __half* dstB = dstA + 128 * GLD;
        #pragma unroll
        for (int i = 0; i < 4; i++) {
            int e = tid + i * 256;
            int r = e >> 3, c8 = e & 7;
            cpa16(smem_u32(dstA + r * GLD + c8 * 8),
                  A + (size_t)(row0 + r) * K + k0 + c8 * 8);
        }
        #pragma unroll
        for (int i = 0; i < 8; i++) {
            int e = tid + i * 256;
            int r = e >> 3, c8 = e & 7;
            cpa16(smem_u32(dstB + r * GLD + c8 * 8),
                  Bt + (size_t)(col0 + r) * K + k0 + c8 * 8);
        }
        asm volatile("cp.async.commit_group;" ::: "memory");
    };

    const int NK = K / 64;
    issue(0, 0);
    issue(1, 1);

    for (int kt = 0; kt < NK; kt++) {
        const int s = kt % 3;
        if (kt == NK - 1) asm volatile("cp.async.wait_group 0;" ::: "memory");
        else              asm volatile("cp.async.wait_group 1;" ::: "memory");
        __syncthreads();
        if (kt + 2 < NK) issue(kt + 2, (kt + 2) % 3);

        const uint32_t sA_u = smh_u + (uint32_t)(s * STAGEH) * 2;
        const uint32_t sB_u = sA_u + (uint32_t)(128 * GLD) * 2;

        #pragma unroll
        for (int ks = 0; ks < 4; ks++) {
            uint32_t a[4][4], b[4][4];
            #pragma unroll
            for (int mi = 0; mi < 4; mi++)
                ldsm_x4(a[mi][0], a[mi][1], a[mi][2], a[mi][3],
                        sA_u + (uint32_t)((aRow + mi*16) * GLD + ks*16 + aCol) * 2);
            #pragma unroll
            for (int ni8 = 0; ni8 < 4; ni8++)
                ldsm_x4(b[ni8][0], b[ni8][1], b[ni8][2], b[ni8][3],
                        sB_u + (uint32_t)((bRow + ni8*16) * GLD + ks*16 + bCol) * 2);
            #pragma unroll
            for (int mi = 0; mi < 4; mi++)
                #pragma unroll
                for (int ni = 0; ni < 8; ni++)
                    mma_f16(acc[mi][ni], a[mi], &b[ni >> 1][(ni & 1) * 2]);
        }
    }

    #pragma unroll
    for (int mi = 0; mi < 4; mi++) {
        #pragma unroll
        for (int hh = 0; hh < 2; hh++) {
            const int r = row0 + m0 + mi * 16 + lq + hh * 8;
            #pragma unroll
            for (int ni = 0; ni < 8; ni++) {
                const int c = col0 + n0 + ni * 8 + 2 * lr;
                float vx = acc[mi][ni][hh * 2 + 0];
                float vy = acc[mi][ni][hh * 2 + 1];
                if (EPI >= 1) { vx += bias[c]; vy += bias[c + 1]; }
                if (EPI == 2) {
                    vx = 0.5f * vx * (1.f + erff(vx * 0.70710678118654752f));
                    vy = 0.5f * vy * (1.f + erff(vy * 0.70710678118654752f));
                }
                if (sizeof(OutT) == 2) {
                    *(__half2*)((__half*)C + (size_t)r * N + c) =
                        __floats2half2_rn(vx, vy);
                } else {
                    *(float2*)((float*)C + (size_t)r * N + c) = make_float2(vx, vy);
                }
            }
        }
    }
}

// ======================= kqv fp16 MMA (K=64, N=192) =========================
// grid M/128 = 512 CTAs, 192 threads = 6 warps of 64x64.
#define KQV_SMEM ((128+192)*GLD*(int)sizeof(__half))   // 46080 B

__global__ __launch_bounds__(192, 2)
void kqv_mma(const __half* __restrict__ xh, const __half* __restrict__ wqt,
             __half* __restrict__ kqv)
{
    extern __shared__ __half smh[];
    const uint32_t smh_u = smem_u32(smh);
    const int tid  = threadIdx.x;
    const int lane = tid & 31;
    const int wid  = tid >> 5;
    const int m0 = (wid & 1) * 64;
    const int n0 = (wid >> 1) * 64;     // 0,64,128
    const int row0 = blockIdx.x * 128;
    const int lq = lane >> 2, lr = lane & 3;
    const int rr = lane & 7, gg = lane >> 3;
    const int aRow = m0 + ((gg & 1) << 3) + rr;
    const int aCol = (gg & 2) << 2;
    const int bRow = n0 + ((gg >> 1) << 3) + rr;
    const int bCol = (gg & 1) << 3;

    __half* sA = smh;
    __half* sB = smh + 128 * GLD;

    for (int e = tid; e < 1024; e += 192) {        // A: 128 rows x 8 chunks
        int r = e >> 3, c8 = e & 7;
        cpa16(smem_u32(sA + r * GLD + c8 * 8),
              xh + (size_t)(row0 + r) * 64 + c8 * 8);
    }
    #pragma unroll
    for (int i = 0; i < 8; i++) {                  // B: 192 rows x 8 chunks
        int e = tid + i * 192;
        int r = e >> 3, c8 = e & 7;
        cpa16(smem_u32(sB + r * GLD + c8 * 8),
              wqt + (size_t)r * 64 + c8 * 8);
    }
    asm volatile("cp.async.commit_group;" ::: "memory");
    asm volatile("cp.async.wait_group 0;" ::: "memory");
    __syncthreads();

    float acc[4][8][4];
    #pragma unroll
    for (int i = 0; i < 4; i++)
        #pragma unroll
        for (int j = 0; j < 8; j++)
            #pragma unroll
            for (int k = 0; k < 4; k++) acc[i][j][k] = 0.f;

    const uint32_t sA_u = smh_u;
    const uint32_t sB_u = smh_u + (uint32_t)(128 * GLD) * 2;

    #pragma unroll
    for (int ks = 0; ks < 4; ks++) {
        uint32_t a[4][4], b[4][4];
        #pragma unroll
        for (int mi = 0; mi < 4; mi++)
            ldsm_x4(a[mi][0], a[mi][1], a[mi][2], a[mi][3],
                    sA_u + (uint32_t)((aRow + mi*16) * GLD + ks*16 + aCol) * 2);
        #pragma unroll
        for (int ni8 = 0; ni8 < 4; ni8++)
            ldsm_x4(b[ni8][0], b[ni8][1], b[ni8][2], b[ni8][3],
                    sB_u + (uint32_t)((bRow + ni8*16) * GLD + ks*16 + bCol) * 2);
        #pragma unroll
        for (int mi = 0; mi < 4; mi++)
            #pragma unroll
            for (int ni = 0; ni < 8; ni++)
                mma_f16(acc[mi][ni], a[mi], &b[ni >> 1][(ni & 1) * 2]);
    }

    #pragma unroll
    for (int mi = 0; mi < 4; mi++) {
        #pragma unroll
        for (int hh = 0; hh < 2; hh++) {
            const int r = row0 + m0 + mi * 16 + lq + hh * 8;
            #pragma unroll
            for (int ni = 0; ni < 8; ni++) {
                const int c = n0 + ni * 8 + 2 * lr;
                *(__half2*)(kqv + (size_t)r * 192 + c) =
                    __floats2half2_rn(acc[mi][ni][hh*2], acc[mi][ni][hh*2+1]);
            }
        }
    }
}

// ---------------- fp16 tensor-core flash attention --------------------------
#define ALD 72
#define ATTN_SMEM ((128*ALD + 2*64*ALD + 2*64*ALD + 128*ALD)*(int)sizeof(__half))

__global__ __launch_bounds__(256, 2)
void attn_mma(const __half* __restrict__ kqv, __half* __restrict__ res)
{
    extern __shared__ __half sma[];
    __half* Qs = sma;                     // 128 x ALD
    __half* Ks = Qs + 128*ALD;            // 2 x 64 x ALD
    __half* Vs = Ks + 2*64*ALD;           // 2 x 64 x ALD
    __half* Ps = Vs + 2*64*ALD;           // 128 x ALD

    const int bh = blockIdx.x;
    const int b  = bh >> 4;
    const int h  = bh & 15;
    const int q0 = blockIdx.y * 128;
    const int tid  = threadIdx.x;
    const int lane = tid & 31;
    const int wid  = tid >> 5;
    const int lq = lane >> 2, lr = lane & 3;
    const int m0 = wid * 16;
    const int rr = lane & 7, gg = lane >> 3;
    const int aRowL = ((gg & 1) << 3) + rr;       // local (0..15)
    const int aCol  = (gg & 2) << 2;
    const int bRowL = ((gg >> 1) << 3) + rr;
    const int bCol  = (gg & 1) << 3;
    const size_t rstr = (size_t)Hh * 3 * Ss;      // 3072 halves
    const __half* base = kqv + (size_t)(b * Tt) * rstr + h * 192;

    const uint32_t ks_u = smem_u32(Ks);
    const uint32_t vs_u = smem_u32(Vs);
    const uint32_t qs_u = smem_u32(Qs);
    const uint32_t ps_u = smem_u32(Ps);

    // load Q tile (q at half-offset 64)
    #pragma unroll
    for (int i = 0; i < 4; i++) {
        int e = tid + i * 256;
        int r = e >> 3, c8 = e & 7;
        cpa16(qs_u + (uint32_t)(r * ALD + c8 * 8) * 2,
              base + (size_t)(q0 + r) * rstr + 64 + c8 * 8);
    }
    asm volatile("cp.async.commit_group;" ::: "memory");

    auto issue_kv = [&](int kt, int s) {
        const __half* kb = base + (size_t)(kt * 64) * rstr;
        #pragma unroll
        for (int i = 0; i < 2; i++) {
            int e = tid + i * 256;
            int r = e >> 3, c8 = e & 7;
            cpa16(ks_u + (uint32_t)((s * 64 + r) * ALD + c8 * 8) * 2,
                  kb + (size_t)r * rstr + c8 * 8);
            cpa16(vs_u + (uint32_t)((s * 64 + r) * ALD + c8 * 8) * 2,
                  kb + (size_t)r * rstr + 128 + c8 * 8);
        }
        asm volatile("cp.async.commit_group;" ::: "memory");
    };

    issue_kv(0, 0);
    asm volatile("cp.async.wait_group 1;" ::: "memory");   // Q done
    __syncthreads();

    // hoist Q fragments via ldmatrix
    uint32_t qf[4][4];
    #pragma unroll
    for (int ks = 0; ks < 4; ks++)
        ldsm_x4(qf[ks][0], qf[ks][1], qf[ks][2], qf[ks][3],
                qs_u + (uint32_t)((m0 + aRowL) * ALD + ks*16 + aCol) * 2);

    float mrow[2] = { -1e30f, -1e30f };
    float lrow[2] = { 0.f, 0.f };
    float acc_o[8][4];
    #pragma unroll
    for (int nf = 0; nf < 8; nf++)
        #pragma unroll
        for (int c = 0; c < 4; c++) acc_o[nf][c] = 0.f;

    const int NT = Tt / 64;
    for (int kt = 0; kt < NT; kt++) {
        const int s = kt & 1;
        if (kt + 1 < NT) {
            issue_kv(kt + 1, s ^ 1);
            asm volatile("cp.async.wait_group 1;" ::: "memory");
        } else {
            asm volatile("cp.async.wait_group 0;" ::: "memory");
        }
        __syncthreads();

        const uint32_t k0_u = ks_u + (uint32_t)(s * 64 * ALD) * 2;

        // S = Q @ K^T
        float acc_s[8][4];
        #pragma unroll
        for (int nf = 0; nf < 8; nf++)
            #pragma unroll
            for (int c = 0; c < 4; c++) acc_s[nf][c] = 0.f;

        #pragma unroll
        for (int ks = 0; ks < 4; ks++) {
            uint32_t b[4][4];
            #pragma unroll
            for (int nf8 = 0; nf8 < 4; nf8++)
                ldsm_x4(b[nf8][0], b[nf8][1], b[nf8][2], b[nf8][3],
                        k0_u + (uint32_t)((bRowL + nf8*16) * ALD + ks*16 + bCol) * 2);
            #pragma unroll
            for (int nf = 0; nf < 8; nf++)
                mma_f16(acc_s[nf], qf[ks], &b[nf >> 1][(nf & 1) * 2]);
        }

        #pragma unroll
        for (int nf = 0; nf < 8; nf++)
            #pragma unroll
            for (int c = 0; c < 4; c++) acc_s[nf][c] *= 0.125f;

        // online softmax; write P (fp16)
        #pragma unroll
        for (int hh = 0; hh < 2; hh++) {
            float rmax = -1e30f;
            #pragma unroll
            for (int nf = 0; nf < 8; nf++)
                rmax = fmaxf(rmax, fmaxf(acc_s[nf][2*hh], acc_s[nf][2*hh+1]));
            rmax = fmaxf(rmax, __shfl_xor_sync(0xffffffffu, rmax, 1));
            rmax = fmaxf(rmax, __shfl_xor_sync(0xffffffffu, rmax, 2));
            float mn = fmaxf(mrow[hh], rmax);
            float scale = __expf(mrow[hh] - mn);
            float rs = 0.f;
            #pragma unroll
            for (int nf = 0; nf < 8; nf++) {
                __half h0 = __float2half_rn(__expf(acc_s[nf][2*hh]   - mn));
                __half h1 = __float2half_rn(__expf(acc_s[nf][2*hh+1] - mn));
                rs += __half2float(h0) + __half2float(h1);
                *(__half2*)&Ps[(size_t)(m0 + lq + 8*hh) * ALD + nf * 8 + 2 * lr] =
                    __halves2half2(h0, h1);
            }
            rs += __shfl_xor_sync(0xffffffffu, rs, 1);
            rs += __shfl_xor_sync(0xffffffffu, rs, 2);
            lrow[hh] = lrow[hh] * scale + rs;
            mrow[hh] = mn;
            #pragma unroll
            for (int nf = 0; nf < 8; nf++) {
                acc_o[nf][2*hh]   *= scale;
                acc_o[nf][2*hh+1] *= scale;
            }
        }
        __syncwarp();

        // O += P @ V
        const uint32_t v0_u = vs_u + (uint32_t)(s * 64 * ALD) * 2;
        #pragma unroll
        for (int ks = 0; ks < 4; ks++) {
            uint32_t a[4];
            ldsm_x4(a[0], a[1], a[2], a[3],
                    ps_u + (uint32_t)((m0 + aRowL) * ALD + ks*16 + aCol) * 2);
            const uint32_t rowaddr = v0_u +
                (uint32_t)((ks * 16 + (lane & 15)) * ALD) * 2;
            #pragma unroll
            for (int nf = 0; nf < 8; nf++) {
                uint32_t b0, b1;
                ldsm_x2_trans(b0, b1, rowaddr + (uint32_t)(nf * 8) * 2);
                uint32_t bfr[2] = { b0, b1 };
                mma_f16(acc_o[nf], a, bfr);
            }
        }
        __syncthreads();
    }

    // epilogue
    #pragma unroll
    for (int hh = 0; hh < 2; hh++) {
        float inv = 1.f / lrow[hh];
        int row = q0 + m0 + lq + 8 * hh;
        __half* orow = res + (size_t)(b * Tt + row) * EMBv + h * 64;
        #pragma unroll
        for (int nf = 0; nf < 8; nf++)
            *(__half2*)(orow + nf * 8 + 2 * lr) =
                __floats2half2_rn(acc_o[nf][2*hh] * inv, acc_o[nf][2*hh+1] * inv);
    }
}

// ---------------- fused residual add + LayerNorm ---------------------------
__global__ __launch_bounds__(256)
void add_ln_kernel(const float* __restrict__ xa, const float* __restrict__ xb,
                   const float* __restrict__ g, const float* __restrict__ bt,
                   float* __restrict__ out, __half* __restrict__ out_r)
{
    const int row = blockIdx.x;
    const int tid = threadIdx.x;
    const float* pa = xa + (size_t)row*EMBv;
    const float* pb = xb + (size_t)row*EMBv;
    float v[4], s = 0.f, s2 = 0.f;
    #pragma unroll
    for (int i = 0; i < 4; i++) {
        int c = tid + i*256;
        v[i] = pa[c] + pb[c];
        s += v[i]; s2 += v[i]*v[i];
    }
    #pragma unroll
    for (int off = 16; off > 0; off >>= 1) {
        s  += __shfl_xor_sync(0xffffffffu, s,  off);
        s2 += __shfl_xor_sync(0xffffffffu, s2, off);
    }
    __shared__ float rs[8], rs2[8];
    int w = tid >> 5, lane = tid & 31;
    if (lane == 0) { rs[w] = s; rs2[w] = s2; }
    __syncthreads();
    if (w == 0) {
        float a  = (lane < 8) ? rs[lane]  : 0.f;
        float a2 = (lane < 8) ? rs2[lane] : 0.f;
        #pragma unroll
        for (int off = 4; off > 0; off >>= 1) {
            a  += __shfl_xor_sync(0xffffffffu, a,  off);
            a2 += __shfl_xor_sync(0xffffffffu, a2, off);
        }
        if (lane == 0) { rs[0] = a; rs2[0] = a2; }
    }
    __syncthreads();
    float mean = rs[0] * (1.f/EMBv);
    float var  = rs2[0] * (1.f/EMBv) - mean*mean;
    float inv  = rsqrtf(var + 1e-5f);
    #pragma unroll
    for (int i = 0; i < 4; i++) {
        int c = tid + i*256;
        float o = (v[i] - mean)*inv*g[c] + bt[c];
        out[(size_t)row*EMBv + c] = o;
        if (out_r) out_r[(size_t)row*EMBv + c] = __float2half_rn(o);
    }
}

// ---------------- launch ----------------------------------------------------
extern "C" void kernel_launch(void* const* d_in, const int* in_sizes, int n_in,
                              void* d_out, int out_size)
{
    const float* x     = (const float*)d_in[0];
    const float* Wkqv  = (const float*)d_in[1];
    const float* Wproj = (const float*)d_in[2];
    const float* g1    = (const float*)d_in[3];
    const float* b1    = (const float*)d_in[4];
    const float* W1    = (const float*)d_in[5];
    const float* bff1  = (const float*)d_in[6];
    const float* W2    = (const float*)d_in[7];
    const float* bff2  = (const float*)d_in[8];
    const float* g2    = (const float*)d_in[9];
    const float* b2    = (const float*)d_in[10];
    float* out = (float*)d_out;

    __half *xh, *kqv, *res, *x1r, *hbuf, *wqt, *wtp, *wt1, *wt2;
    float  *mha, *x1, *ff;
    cudaGetSymbolAddress((void**)&xh,   g_xh);
    cudaGetSymbolAddress((void**)&kqv,  g_kqv);
    cudaGetSymbolAddress((void**)&res,  g_res);
    cudaGetSymbolAddress((void**)&mha,  g_mha);
    cudaGetSymbolAddress((void**)&x1,   g_x1);
    cudaGetSymbolAddress((void**)&x1r,  g_x1r);
    cudaGetSymbolAddress((void**)&hbuf, g_h);
    cudaGetSymbolAddress((void**)&ff,   g_ff);
    cudaGetSymbolAddress((void**)&wqt,  g_wqt);
    cudaGetSymbolAddress((void**)&wtp,  g_wtp);
    cudaGetSymbolAddress((void**)&wt1,  g_wt1);
    cudaGetSymbolAddress((void**)&wt2,  g_wt2);

    cudaFuncSetAttribute((const void*)mma_gemm<0,float>,
        cudaFuncAttributeMaxDynamicSharedMemorySize, MMA_SMEM);
    cudaFuncSetAttribute((const void*)mma_gemm<1,float>,
        cudaFuncAttributeMaxDynamicSharedMemorySize, MMA_SMEM);
    cudaFuncSetAttribute((const void*)mma_gemm<2,__half>,
        cudaFuncAttributeMaxDynamicSharedMemorySize, MMA_SMEM);
    cudaFuncSetAttribute((const void*)attn_mma,
        cudaFuncAttributeMaxDynamicSharedMemorySize, ATTN_SMEM);
    cudaFuncSetAttribute((const void*)kqv_mma,
        cudaFuncAttributeMaxDynamicSharedMemorySize, KQV_SMEM);

    // 0) x -> fp16; transpose + fp16 weights
    cvt_half_kernel<<<(NTOK*EMBv/4 + 255)/256, 256>>>(
        (const float4*)x, (__half2*)xh, NTOK*EMBv/4);
    transpose_kernel<<<dim3(192/32, Ss/32),   dim3(32,8)>>>(Wkqv,  wqt, Ss,   192);
    transpose_kernel<<<dim3(EMBv/32, EMBv/32), dim3(32,8)>>>(Wproj, wtp, EMBv, EMBv);
    transpose_kernel<<<dim3(FF/32,   EMBv/32), dim3(32,8)>>>(W1,    wt1, EMBv, FF);
    transpose_kernel<<<dim3(EMBv/32, FF/32),   dim3(32,8)>>>(W2,    wt2, FF,   EMBv);

    // 1) kqv (fp16 tensor cores)
    kqv_mma<<<(NTOK*Hh)/128, 192, KQV_SMEM>>>(xh, wqt, kqv);

    // 2) attention
    attn_mma<<<dim3(Bb*Hh, Tt/128), 256, ATTN_SMEM>>>(kqv, res);

    // 3) mha = res @ Wproj
    mma_gemm<0,float><<<dim3(EMBv/256, NTOK/128), 256, MMA_SMEM>>>(
        res, wtp, nullptr, mha, NTOK, EMBv, EMBv);

    // 4) x1 = LN(x + mha)  (+fp16 copy)
    add_ln_kernel<<<NTOK, 256>>>(x, mha, g1, b1, x1, x1r);

    // 5) h = gelu(x1 @ W1 + bff1)
    mma_gemm<2,__half><<<dim3(FF/256, NTOK/128), 256, MMA_SMEM>>>(
        x1r, wt1, bff1, hbuf, NTOK, FF, EMBv);

    // 6) ff = h @ W2 + bff2
    mma_gemm<1,float><<<dim3(EMBv/256, NTOK/128), 256, MMA_SMEM>>>(
        hbuf, wt2, bff2, ff, NTOK, EMBv, FF);

    // 7) out = LN(x1 + ff)
    add_ln_kernel<<<NTOK, 256>>>(x1, ff, g2, b2, out, nullptr);
}